// round 11
// baseline (speedup 1.0000x reference)
#include <cuda_runtime.h>
#include <cuda_bf16.h>
#include <math.h>
#include <stdint.h>

typedef unsigned int u32;
typedef unsigned long long u64;

#define BMAX 65536

// ---------------------------------------------------------------------------
// Device scratch.
//  g_att : attention out (pre-residual) bf16 [3B, 256]
//  g_hh  : LN2(fused) split bf16             [B, 512]  (hi | lo)
//  g_w   : split weights                     [rows, 512]
// ---------------------------------------------------------------------------
__device__ __nv_bfloat16 g_att[(size_t)BMAX * 3 * 256];
__device__ __nv_bfloat16 g_hh [(size_t)BMAX * 512];
__device__ __nv_bfloat16 g_w  [(size_t)(768 + 256 + 256 + 128) * 512];

#define WOFF_QKV 0
#define WOFF_OUT (768 * 512)
#define WOFF_W1  ((768 + 256) * 512)
#define WOFF_W2  ((768 + 512) * 512)

__device__ __forceinline__ u32 smem_u32(const void* p) {
    u32 a;
    asm("{ .reg .u64 t; cvta.to.shared.u64 t, %1; cvt.u32.u64 %0, t; }" : "=r"(a) : "l"(p));
    return a;
}
__device__ __forceinline__ float geluf(float x) {
    return 0.5f * x * (1.0f + erff(x * 0.7071067811865476f));
}
__device__ __forceinline__ float wsum(float v) {
    #pragma unroll
    for (int o = 16; o > 0; o >>= 1) v += __shfl_xor_sync(0xffffffffu, v, o);
    return v;
}
__device__ __forceinline__ u32 bf2bits(__nv_bfloat162 h) {
    return *reinterpret_cast<u32*>(&h);
}
__device__ __forceinline__ void split2(float a, float b, u32& h, u32& l) {
    __nv_bfloat162 hh = __floats2bfloat162_rn(a, b);
    float ra = a - __bfloat162float(hh.x);
    float rb = b - __bfloat162float(hh.y);
    __nv_bfloat162 ll = __floats2bfloat162_rn(ra, rb);
    h = bf2bits(hh);
    l = bf2bits(ll);
}

// ---------------------------------------------------------------------------
// merged weight conversion: fp32 [rows,256] -> split bf16 [rows,512]
// ---------------------------------------------------------------------------
__global__ __launch_bounds__(256)
void conv_w_all(const float* __restrict__ ipw, const float* __restrict__ ow,
                const float* __restrict__ w1, const float* __restrict__ w2)
{
    int id = blockIdx.x * 256 + threadIdx.x;
    int row = id >> 6;
    int k = (id & 63) << 2;
    const float* src; int r, woff;
    if (row < 768)       { src = ipw; r = row;        woff = WOFF_QKV; }
    else if (row < 1024) { src = ow;  r = row - 768;  woff = WOFF_OUT; }
    else if (row < 1280) { src = w1;  r = row - 1024; woff = WOFF_W1; }
    else                 { src = w2;  r = row - 1280; woff = WOFF_W2; }
    float4 v = *(const float4*)(src + (size_t)r * 256 + k);
    u32 h0, l0, h1, l1;
    split2(v.x, v.y, h0, l0);
    split2(v.z, v.w, h1, l1);
    __nv_bfloat16* dst = g_w + (size_t)woff + (size_t)r * 512;
    u32* hp = (u32*)(dst + k);
    u32* lp = (u32*)(dst + 256 + k);
    hp[0] = h0; hp[1] = h1;
    lp[0] = l0; lp[1] = l1;
}

// ---------------------------------------------------------------------------
// MMA helpers
// ---------------------------------------------------------------------------
__device__ __forceinline__ void ldsm4(u32 addr, u32& r0, u32& r1, u32& r2, u32& r3) {
    asm volatile("ldmatrix.sync.aligned.m8n8.x4.shared.b16 {%0,%1,%2,%3}, [%4];"
                 : "=r"(r0), "=r"(r1), "=r"(r2), "=r"(r3) : "r"(addr));
}
__device__ __forceinline__ void mma16816(float* c, const u32* a, u32 b0, u32 b1) {
    asm volatile(
        "mma.sync.aligned.m16n8k16.row.col.f32.bf16.bf16.f32 "
        "{%0,%1,%2,%3}, {%4,%5,%6,%7}, {%8,%9}, {%0,%1,%2,%3};"
        : "+f"(c[0]), "+f"(c[1]), "+f"(c[2]), "+f"(c[3])
        : "r"(a[0]), "r"(a[1]), "r"(a[2]), "r"(a[3]), "r"(b0), "r"(b1));
}

// load NROWS x 128B chunk into SW128-swizzled smem via cp.async
template<int NROWS, int ROWB>
__device__ __forceinline__ void load_tile(u32 sbase, const char* gb) {
    constexpr int ITERS = NROWS * 8 / 256;
    int tid = threadIdx.x;
    #pragma unroll
    for (int i = 0; i < ITERS; i++) {
        int seg = i * 256 + tid;
        int r = seg >> 3, c = seg & 7;
        u32 off = (u32)(r * 128 + c * 16);
        off ^= (off >> 3) & 0x70;
        asm volatile("cp.async.cg.shared.global [%0], [%1], 16;"
                     :: "r"(sbase + off), "l"(gb + (size_t)r * ROWB + c * 16));
    }
}

// 48-row feature chunk: fp32 -> bf16 direct into swizzled smem
__device__ __forceinline__ void load_Afeat48(u32 sbase, int m0, int c,
                                             const float* __restrict__ s0,
                                             const float* __restrict__ s1,
                                             const float* __restrict__ s2)
{
    int tid = threadIdx.x;
    #pragma unroll
    for (int i = 0; i < 2; i++) {
        int seg = i * 256 + tid;          // 384 segs of 16B bf16 (=8 floats)
        if (seg < 384) {
            int r = seg >> 3, c8 = seg & 7;
            int m = m0 + r;
            int b = m / 3, t = m - 3 * b;
            const float* src = ((t == 0) ? s0 : (t == 1) ? s1 : s2)
                               + (size_t)b * 256 + c * 64 + c8 * 8;
            float4 v0 = *(const float4*)src;
            float4 v1 = *(const float4*)(src + 4);
            u32 w0 = bf2bits(__floats2bfloat162_rn(v0.x, v0.y));
            u32 w1 = bf2bits(__floats2bfloat162_rn(v0.z, v0.w));
            u32 w2 = bf2bits(__floats2bfloat162_rn(v1.x, v1.y));
            u32 w3 = bf2bits(__floats2bfloat162_rn(v1.z, v1.w));
            u32 off = (u32)(r * 128 + c8 * 16);
            off ^= (off >> 3) & 0x70;
            asm volatile("st.shared.v4.b32 [%0], {%1,%2,%3,%4};"
                         :: "r"(sbase + off), "r"(w0), "r"(w1), "r"(w2), "r"(w3));
        }
    }
}

// one K-chunk of MMA for 48x16 warp tile (1m x 8n org): acc[3][2][4]
__device__ __forceinline__ void mma_chunk48(float (&acc)[3][2][4],
                                            u32 As, u32 Bs,
                                            int a_row_base, int a_kb_sel,
                                            int b_row_base, int b_kb_sel,
                                            int warp_n)
{
    #pragma unroll
    for (int ks = 0; ks < 4; ks++) {
        u32 a[3][4];
        #pragma unroll
        for (int fm = 0; fm < 3; fm++) {
            int row = fm * 16 + a_row_base;
            u32 kb = (u32)(ks * 32 + a_kb_sel);
            u32 ad = As + row * 128 + (kb ^ ((row & 7) << 4));
            ldsm4(ad, a[fm][0], a[fm][1], a[fm][2], a[fm][3]);
        }
        u32 b[4];
        {
            int row = warp_n * 16 + b_row_base;
            u32 kb = (u32)(ks * 32 + b_kb_sel);
            u32 bd = Bs + row * 128 + (kb ^ ((row & 7) << 4));
            ldsm4(bd, b[0], b[1], b[2], b[3]);
        }
        #pragma unroll
        for (int fm = 0; fm < 3; fm++) {
            mma16816(acc[fm][0], a[fm], b[0], b[1]);
            mma16816(acc[fm][1], a[fm], b[2], b[3]);
        }
    }
}

// ---------------------------------------------------------------------------
// qkv_attn_out (occ 2): M_TILE = 48 rows = 16 batches, per-head-pair passes.
//  pass p: qkv n-tiles {p, 2+p, 4+p} -> park P; attention heads 2p,2p+1 ->
//  ctx half -> C; partial out-proj over 2 K-chunks accumulated in registers.
// smem: A 4x6144 (24K) | W 2x16384 (32K) | P 3x12288 (36.9K) | C 2x6144 (12.3K)
//     = 106.5K  -> 2 CTAs/SM
// ---------------------------------------------------------------------------
__global__ __launch_bounds__(256, 2)
void qkv_attn_out(const float* __restrict__ ipb, const float* __restrict__ ob,
                  const float* __restrict__ s0, const float* __restrict__ s1,
                  const float* __restrict__ s2)
{
    extern __shared__ char dsm[];
    char* dbase = (char*)((((uintptr_t)dsm) + 127) & ~(uintptr_t)127);
    u32 base = smem_u32(dbase);
    const u32 abase = base;                 // 4 x 6144
    const u32 wbase = base + 24576;         // 2 x 16384
    char* Pd = dbase + 57344;               // 3 x 12288, row-major 256B
    const u32 cbase = base + 94208;         // 2 x 6144 (GEMM chunks)

    const int tid = threadIdx.x;
    const int lane = tid & 31;
    const int wid = tid >> 5;
    const int warp_n = wid;                 // 1m x 8n, warp tile 48x16
    const int m0 = blockIdx.x * 48;

    const char* Wq = (const char*)(g_w + WOFF_QKV);
    const char* Wo = (const char*)(g_w + WOFF_OUT);

    const int a_mi = lane >> 3;
    const int a_row_base = ((a_mi & 1) << 3) + (lane & 7);
    const int a_kb_sel = (lane >> 4) << 4;
    const int b_row_base = ((a_mi >> 1) << 3) + (lane & 7);
    const int b_kb_sel = ((lane >> 3) & 1) << 4;
    const int quad = lane >> 2, tq = lane & 3;

    float opacc[2][3][2][4];
    #pragma unroll
    for (int i = 0; i < 2; i++)
        #pragma unroll
        for (int j = 0; j < 3; j++)
            #pragma unroll
            for (int q = 0; q < 2; q++)
                #pragma unroll
                for (int r = 0; r < 4; r++) opacc[i][j][q][r] = 0.f;
    float qacc[3][2][4];
    #pragma unroll
    for (int j = 0; j < 3; j++)
        #pragma unroll
        for (int q = 0; q < 2; q++)
            #pragma unroll
            for (int r = 0; r < 4; r++) qacc[j][q][r] = 0.f;

    // resident A: features fp32 -> bf16, 4 chunks
    #pragma unroll
    for (int c = 0; c < 4; c++)
        load_Afeat48(abase + c * 6144, m0, c, s0, s1, s2);

    // W prologue: g=0 (pass0, q-subtile, chunk 0)
    load_tile<128, 1024>(wbase, Wq);
    asm volatile("cp.async.commit_group;");
    __syncthreads();

    // chunk address schedule (32 chunks)
    #pragma unroll 1
    for (int g = 0; g < 32; g++) {
        if (g + 1 < 32) {
            const int g1 = g + 1;
            const char* nw;
            if (g1 < 12)      nw = Wq + (size_t)((g1 >> 2) * 2 + 0) * 131072 + (g1 & 3) * 128;
            else if (g1 < 16) { int j = g1 - 12; nw = Wo + (size_t)(j >> 1) * 131072 + (j & 1) * 128; }
            else if (g1 < 28) { int j = g1 - 16; nw = Wq + (size_t)((j >> 2) * 2 + 1) * 131072 + (j & 3) * 128; }
            else              { int j = g1 - 28; nw = Wo + (size_t)(j >> 1) * 131072 + (2 + (j & 1)) * 128; }
            load_tile<128, 1024>(wbase + (g1 & 1) * 16384, nw);
            asm volatile("cp.async.commit_group;");
            asm volatile("cp.async.wait_group 1;");
        } else {
            asm volatile("cp.async.wait_group 0;");
        }
        __syncthreads();

        const bool is_qkv = (g < 12) || (g >= 16 && g < 28);
        const u32 Bs = wbase + (g & 1) * 16384;

        if (is_qkv) {
            const int p = (g < 12) ? 0 : 1;
            const int gl = (g < 12) ? g : (g - 16);
            const int s = gl >> 2, kc = gl & 3;
            mma_chunk48(qacc, abase + kc * 6144, Bs,
                        a_row_base, a_kb_sel, b_row_base, b_kb_sel, warp_n);
            __syncthreads();

            if (kc == 3) {
                // park epilogue: +bias, bf16 -> P slot s (row-major 256B)
                #pragma unroll
                for (int fm = 0; fm < 3; fm++) {
                    const int r = fm * 16 + quad;
                    #pragma unroll
                    for (int f8 = 0; f8 < 2; f8++) {
                        const int ncol = warp_n * 16 + f8 * 8 + 2 * tq;
                        const int gcol = (s * 2 + p) * 128 + ncol;
                        float2 bv = *(const float2*)&ipb[gcol];
                        u32 lo = bf2bits(__floats2bfloat162_rn(qacc[fm][f8][0] + bv.x,
                                                               qacc[fm][f8][1] + bv.y));
                        u32 hi = bf2bits(__floats2bfloat162_rn(qacc[fm][f8][2] + bv.x,
                                                               qacc[fm][f8][3] + bv.y));
                        char* prow = Pd + s * 12288;
                        *(u32*)(prow + (size_t)r * 256 + ncol * 2)       = lo;
                        *(u32*)(prow + (size_t)(r + 8) * 256 + ncol * 2) = hi;
                        qacc[fm][f8][0] = 0.f; qacc[fm][f8][1] = 0.f;
                        qacc[fm][f8][2] = 0.f; qacc[fm][f8][3] = 0.f;
                    }
                }

                if (s == 2) {
                    __syncthreads();
                    // -------- attention for head pair p --------
                    const int hl = lane >> 4;         // head within pair
                    const int sl = lane & 15;
                    const int cb = (hl * 64 + sl * 4) * 2;   // byte col in half
                    #pragma unroll 1
                    for (int bl = 0; bl < 2; bl++) {
                        const int tb = wid * 2 + bl;
                        float q[3][4], k[3][4], v[3][4];
                        #pragma unroll
                        for (int t = 0; t < 3; t++) {
                            const int row = tb * 3 + t;
                            u64 qr = *(const u64*)(Pd + 0     + (size_t)row * 256 + cb);
                            u64 kr = *(const u64*)(Pd + 12288 + (size_t)row * 256 + cb);
                            u64 vr = *(const u64*)(Pd + 24576 + (size_t)row * 256 + cb);
                            u32 qw[2] = {(u32)qr, (u32)(qr >> 32)};
                            u32 kw[2] = {(u32)kr, (u32)(kr >> 32)};
                            u32 vw[2] = {(u32)vr, (u32)(vr >> 32)};
                            #pragma unroll
                            for (int j = 0; j < 2; j++) {
                                float2 qf = __bfloat1622float2(*(const __nv_bfloat162*)&qw[j]);
                                float2 kf = __bfloat1622float2(*(const __nv_bfloat162*)&kw[j]);
                                float2 vf = __bfloat1622float2(*(const __nv_bfloat162*)&vw[j]);
                                q[t][2*j] = qf.x; q[t][2*j+1] = qf.y;
                                k[t][2*j] = kf.x; k[t][2*j+1] = kf.y;
                                v[t][2*j] = vf.x; v[t][2*j+1] = vf.y;
                            }
                        }
                        float sc[3][3];
                        #pragma unroll
                        for (int t = 0; t < 3; t++)
                            #pragma unroll
                            for (int u = 0; u < 3; u++) {
                                float pv = 0.f;
                                #pragma unroll
                                for (int j = 0; j < 4; j++) pv += q[t][j] * k[u][j];
                                pv += __shfl_xor_sync(0xffffffffu, pv, 1);
                                pv += __shfl_xor_sync(0xffffffffu, pv, 2);
                                pv += __shfl_xor_sync(0xffffffffu, pv, 4);
                                pv += __shfl_xor_sync(0xffffffffu, pv, 8);
                                sc[t][u] = pv * 0.125f;
                            }
                        #pragma unroll
                        for (int t = 0; t < 3; t++) {
                            float mx = fmaxf(sc[t][0], fmaxf(sc[t][1], sc[t][2]));
                            float e0 = expf(sc[t][0] - mx);
                            float e1 = expf(sc[t][1] - mx);
                            float e2 = expf(sc[t][2] - mx);
                            float inv = 1.f / (e0 + e1 + e2);
                            u32 cw0, cw1;
                            {
                                float c0 = (e0 * v[0][0] + e1 * v[1][0] + e2 * v[2][0]) * inv;
                                float c1 = (e0 * v[0][1] + e1 * v[1][1] + e2 * v[2][1]) * inv;
                                float c2 = (e0 * v[0][2] + e1 * v[1][2] + e2 * v[2][2]) * inv;
                                float c3 = (e0 * v[0][3] + e1 * v[1][3] + e2 * v[2][3]) * inv;
                                cw0 = bf2bits(__floats2bfloat162_rn(c0, c1));
                                cw1 = bf2bits(__floats2bfloat162_rn(c2, c3));
                            }
                            // ctx -> C chunks (GEMM-operand layout, swizzled)
                            const int row = tb * 3 + t;
                            u32 off = (u32)(row * 128 + sl * 8);
                            off ^= (off >> 3) & 0x70;
                            asm volatile("st.shared.v2.b32 [%0], {%1,%2};"
                                         :: "r"(cbase + hl * 6144 + off),
                                            "r"(cw0), "r"(cw1));
                        }
                    }
                    __syncthreads();
                }
            }
        } else {
            // partial out-proj: ctx half x out_w chunk
            const int j = (g < 16) ? (g - 12) : (g - 28);
            const int nt2 = j >> 1, kcc = j & 1;
            mma_chunk48(opacc[nt2], cbase + kcc * 6144, Bs,
                        a_row_base, a_kb_sel, b_row_base, b_kb_sel, warp_n);
            __syncthreads();
        }
    }

    // final epilogue: opacc + out_b -> g_att bf16
    #pragma unroll
    for (int nt2 = 0; nt2 < 2; nt2++) {
        #pragma unroll
        for (int fm = 0; fm < 3; fm++) {
            const int r = m0 + fm * 16 + quad;
            #pragma unroll
            for (int f8 = 0; f8 < 2; f8++) {
                const int ncol = nt2 * 128 + warp_n * 16 + f8 * 8 + 2 * tq;
                float2 bv = *(const float2*)&ob[ncol];
                u32 lo = bf2bits(__floats2bfloat162_rn(opacc[nt2][fm][f8][0] + bv.x,
                                                       opacc[nt2][fm][f8][1] + bv.y));
                u32 hi = bf2bits(__floats2bfloat162_rn(opacc[nt2][fm][f8][2] + bv.x,
                                                       opacc[nt2][fm][f8][3] + bv.y));
                *(u32*)&g_att[(size_t)r * 256 + ncol]       = lo;
                *(u32*)&g_att[(size_t)(r + 8) * 256 + ncol] = hi;
            }
        }
    }
}

// ---------------------------------------------------------------------------
// fuse: x = att(bf16) + feat; LN1, gate softmax, fused (fp32), LN2 -> g_hh.
// ---------------------------------------------------------------------------
__global__ __launch_bounds__(256)
void fuse_k(const float* __restrict__ s0, const float* __restrict__ s1,
            const float* __restrict__ s2,
            const float* __restrict__ ln1g, const float* __restrict__ ln1b,
            const float* __restrict__ gw,   const float* __restrict__ gb,
            const float* __restrict__ ln2g, const float* __restrict__ ln2b,
            float* __restrict__ out_fused, int B)
{
    __shared__ float s_gw[2304];
    __shared__ float s_ln[1024];
    for (int i = threadIdx.x; i < 2304; i += 256) s_gw[i] = gw[i];
    if (threadIdx.x < 256) {
        int i = threadIdx.x;
        s_ln[i]       = ln1g[i];
        s_ln[256 + i] = ln1b[i];
        s_ln[512 + i] = ln2g[i];
        s_ln[768 + i] = ln2b[i];
    }
    __syncthreads();

    int warp = threadIdx.x >> 5, lane = threadIdx.x & 31;
    int d0 = lane * 8;
    const float* srcs[3] = {s0, s1, s2};

    for (int b = blockIdx.x * 8 + warp; b < B; b += gridDim.x * 8) {
        float y[3][8];
        float gpart[3] = {0.f, 0.f, 0.f};
        #pragma unroll
        for (int t = 0; t < 3; t++) {
            float iv[8];
            const float* in = srcs[t] + (size_t)b * 256;
            *(float4*)&iv[0] = *(const float4*)(in + d0);
            *(float4*)&iv[4] = *(const float4*)(in + d0 + 4);
            float x[8];
            uint4 ar = *(const uint4*)(g_att + ((size_t)b * 3 + t) * 256 + d0);
            const u32* aw = (const u32*)&ar;
            #pragma unroll
            for (int j = 0; j < 4; j++) {
                float2 af = __bfloat1622float2(*(const __nv_bfloat162*)&aw[j]);
                x[2*j]   = af.x + iv[2*j];
                x[2*j+1] = af.y + iv[2*j+1];
            }
            float s = 0.f;
            #pragma unroll
            for (int j = 0; j < 8; j++) s += x[j];
            s = wsum(s);
            float mu = s * (1.f / 256.f);
            float vv = 0.f;
            #pragma unroll
            for (int j = 0; j < 8; j++) { float d = x[j] - mu; vv += d * d; }
            vv = wsum(vv);
            float rs = rsqrtf(vv * (1.f / 256.f) + 1e-5f);
            #pragma unroll
            for (int j = 0; j < 8; j++)
                y[t][j] = (x[j] - mu) * rs * s_ln[d0 + j] + s_ln[256 + d0 + j];

            #pragma unroll
            for (int g = 0; g < 3; g++) {
                const float* wrow = s_gw + g * 768 + t * 256 + d0;
                #pragma unroll
                for (int j = 0; j < 8; j++) gpart[g] += iv[j] * wrow[j];
            }
        }
        float gl[3];
        #pragma unroll
        for (int g = 0; g < 3; g++) gl[g] = wsum(gpart[g]) + gb[g];
        float mx = fmaxf(gl[0], fmaxf(gl[1], gl[2]));
        float e0 = expf(gl[0] - mx), e1 = expf(gl[1] - mx), e2 = expf(gl[2] - mx);
        float inv = 1.f / (e0 + e1 + e2);
        float w0 = e0 * inv, w1 = e1 * inv, w2 = e2 * inv;

        float f[8];
        #pragma unroll
        for (int j = 0; j < 8; j++)
            f[j] = w0 * y[0][j] + w1 * y[1][j] + w2 * y[2][j];
        if (out_fused) {
            float* orow = out_fused + (size_t)b * 256 + d0;
            *(float4*)orow       = *(float4*)&f[0];
            *(float4*)(orow + 4) = *(float4*)&f[4];
        }
        float s2v = 0.f;
        #pragma unroll
        for (int j = 0; j < 8; j++) s2v += f[j];
        s2v = wsum(s2v);
        float mu2 = s2v * (1.f / 256.f);
        float vv2 = 0.f;
        #pragma unroll
        for (int j = 0; j < 8; j++) { float d = f[j] - mu2; vv2 += d * d; }
        vv2 = wsum(vv2);
        float rs2 = rsqrtf(vv2 * (1.f / 256.f) + 1e-5f);
        u32 hi[4], lo[4];
        #pragma unroll
        for (int j = 0; j < 8; j += 2) {
            float h0 = (f[j]   - mu2) * rs2 * s_ln[512 + d0 + j]   + s_ln[768 + d0 + j];
            float h1 = (f[j+1] - mu2) * rs2 * s_ln[512 + d0 + j+1] + s_ln[768 + d0 + j+1];
            split2(h0, h1, hi[j >> 1], lo[j >> 1]);
        }
        __nv_bfloat16* hrow = g_hh + (size_t)b * 512 + d0;
        *(uint4*)hrow         = *(uint4*)hi;
        *(uint4*)(hrow + 256) = *(uint4*)lo;
    }
}

// ---------------------------------------------------------------------------
// deephead (occ-2): M_TILE=64, A streamed (2x8K), W streamed (2x16K),
// H2 resident (8x8K = 64K). Total 112K -> 2 CTAs/SM.
// ---------------------------------------------------------------------------
__global__ __launch_bounds__(256, 2)
void deephead(const float* __restrict__ b1, const float* __restrict__ b2,
              const float* __restrict__ w3p, const float* __restrict__ b3p,
              float* __restrict__ outp)
{
    extern __shared__ char dsm[];
    char* dbase = (char*)((((uintptr_t)dsm) + 127) & ~(uintptr_t)127);
    u32 base = smem_u32(dbase);
    const u32 abase = base;              // 2 x 8192
    const u32 wbase = base + 16384;      // 2 x 16384
    const u32 hbase = base + 49152;      // 8 x 8192

    const int tid = threadIdx.x;
    const int lane = tid & 31;
    const int wid = tid >> 5;
    const int warp_m = wid & 1;
    const int warp_n = wid >> 1;
    const int m0 = blockIdx.x * 64;

    const char* Ab  = (const char*)g_hh + (size_t)m0 * 1024;
    const char* W1b = (const char*)(g_w + WOFF_W1);
    const char* W2b = (const char*)(g_w + WOFF_W2);

    const int a_idx12[12] = {0,1,2,3, 0,1,2,3, 4,5,6,7};
    const int w_idx12[12] = {0,1,2,3, 4,5,6,7, 0,1,2,3};

    const int a_mi = lane >> 3;
    const int a_row_base = ((a_mi & 1) << 3) + (lane & 7);
    const int a_kb_sel = (lane >> 4) << 4;
    const int b_row_base = ((a_mi >> 1) << 3) + (lane & 7);
    const int b_kb_sel = ((lane >> 3) & 1) << 4;
    const int quad = lane >> 2, tq = lane & 3;

    float acc[2][4][4];
    #pragma unroll
    for (int i = 0; i < 2; i++)
        #pragma unroll
        for (int j = 0; j < 4; j++)
            #pragma unroll
            for (int q = 0; q < 4; q++) acc[i][j][q] = 0.f;

    load_tile<64, 1024>(abase, Ab);
    load_tile<128, 1024>(wbase, W1b);
    asm volatile("cp.async.commit_group;");

    // ---------------- phase 1: h2 = GELU(hh @ w1^T + b1) --------------------
    #pragma unroll 1
    for (int g = 0; g < 24; g++) {
        const int nt = g / 12, kc = g - nt * 12;
        if (g < 23) {
            const int g1 = g + 1;
            const int nt1 = g1 / 12, kc1 = g1 - nt1 * 12;
            load_tile<64, 1024>(abase + (g1 & 1) * 8192, Ab + a_idx12[kc1] * 128);
            load_tile<128, 1024>(wbase + (g1 & 1) * 16384,
                                 W1b + (size_t)nt1 * 131072 + w_idx12[kc1] * 128);
        } else {
            load_tile<128, 1024>(wbase, W2b + w_idx12[0] * 128);
        }
        asm volatile("cp.async.commit_group;");
        asm volatile("cp.async.wait_group 1;");
        __syncthreads();

        const u32 As = abase + (g & 1) * 8192;
        const u32 Bs = wbase + (g & 1) * 16384;
        #pragma unroll
        for (int ks = 0; ks < 4; ks++) {
            u32 a[2][4];
            #pragma unroll
            for (int fm = 0; fm < 2; fm++) {
                int row = warp_m * 32 + fm * 16 + a_row_base;
                u32 kb = (u32)(ks * 32 + a_kb_sel);
                u32 ad = As + row * 128 + (kb ^ ((row & 7) << 4));
                ldsm4(ad, a[fm][0], a[fm][1], a[fm][2], a[fm][3]);
            }
            u32 b[2][4];
            #pragma unroll
            for (int fn = 0; fn < 2; fn++) {
                int row = warp_n * 32 + fn * 16 + b_row_base;
                u32 kb = (u32)(ks * 32 + b_kb_sel);
                u32 bd = Bs + row * 128 + (kb ^ ((row & 7) << 4));
                ldsm4(bd, b[fn][0], b[fn][1], b[fn][2], b[fn][3]);
            }
            #pragma unroll
            for (int fm = 0; fm < 2; fm++)
                #pragma unroll
                for (int f8 = 0; f8 < 4; f8++)
                    mma16816(acc[fm][f8], a[fm],
                             b[f8 >> 1][(f8 & 1) * 2], b[f8 >> 1][(f8 & 1) * 2 + 1]);
        }
        __syncthreads();

        if (kc == 11) {
            #pragma unroll
            for (int fm = 0; fm < 2; fm++) {
                #pragma unroll
                for (int f8 = 0; f8 < 4; f8++) {
                    const int ncol = nt * 128 + warp_n * 32 + f8 * 8 + 2 * tq;
                    float2 bv = *(const float2*)&b1[ncol];
                    float v0 = geluf(acc[fm][f8][0] + bv.x);
                    float v1 = geluf(acc[fm][f8][1] + bv.y);
                    float v2 = geluf(acc[fm][f8][2] + bv.x);
                    float v3 = geluf(acc[fm][f8][3] + bv.y);
                    u32 h0, l0, h1, l1;
                    split2(v0, v1, h0, l0);
                    split2(v2, v3, h1, l1);
                    const int chl = ncol >> 6;
                    const u32 hi_slot = hbase + chl * 8192;
                    const u32 lo_slot = hbase + 32768 + chl * 8192;
                    const int bb = (ncol & 63) * 2;
                    const int r0 = warp_m * 32 + fm * 16 + quad;
                    #pragma unroll
                    for (int wh = 0; wh < 2; wh++) {
                        int row = r0 + wh * 8;
                        u32 off = (u32)(row * 128 + (bb & ~15));
                        off ^= (off >> 3) & 0x70;
                        off += (u32)(bb & 15);
                        u32 hv = wh ? h1 : h0;
                        u32 lv = wh ? l1 : l0;
                        asm volatile("st.shared.b32 [%0], %1;" :: "r"(hi_slot + off), "r"(hv));
                        asm volatile("st.shared.b32 [%0], %1;" :: "r"(lo_slot + off), "r"(lv));
                    }
                    acc[fm][f8][0] = 0.f; acc[fm][f8][1] = 0.f;
                    acc[fm][f8][2] = 0.f; acc[fm][f8][3] = 0.f;
                }
            }
        }
    }

    // ---------------- phase 2: h3 = GELU(h2 @ w2^T + b2) --------------------
    #pragma unroll 1
    for (int j = 0; j < 12; j++) {
        if (j < 11) {
            load_tile<128, 1024>(wbase + ((25 + j) & 1) * 16384,
                                 W2b + w_idx12[j + 1] * 128);
            asm volatile("cp.async.commit_group;");
            asm volatile("cp.async.wait_group 1;");
        } else {
            asm volatile("cp.async.wait_group 0;");
        }
        __syncthreads();

        const u32 As = hbase + a_idx12[j] * 8192;
        const u32 Bs = wbase + ((24 + j) & 1) * 16384;
        #pragma unroll
        for (int ks = 0; ks < 4; ks++) {
            u32 a[2][4];
            #pragma unroll
            for (int fm = 0; fm < 2; fm++) {
                int row = warp_m * 32 + fm * 16 + a_row_base;
                u32 kb = (u32)(ks * 32 + a_kb_sel);
                u32 ad = As + row * 128 + (kb ^ ((row & 7) << 4));
                ldsm4(ad, a[fm][0], a[fm][1], a[fm][2], a[fm][3]);
            }
            u32 b[2][4];
            #pragma unroll
            for (int fn = 0; fn < 2; fn++) {
                int row = warp_n * 32 + fn * 16 + b_row_base;
                u32 kb = (u32)(ks * 32 + b_kb_sel);
                u32 bd = Bs + row * 128 + (kb ^ ((row & 7) << 4));
                ldsm4(bd, b[fn][0], b[fn][1], b[fn][2], b[fn][3]);
            }
            #pragma unroll
            for (int fm = 0; fm < 2; fm++)
                #pragma unroll
                for (int f8 = 0; f8 < 4; f8++)
                    mma16816(acc[fm][f8], a[fm],
                             b[f8 >> 1][(f8 & 1) * 2], b[f8 >> 1][(f8 & 1) * 2 + 1]);
        }
        __syncthreads();
    }

    float* h3_s = (float*)(dbase + 49152);
    #pragma unroll
    for (int fm = 0; fm < 2; fm++) {
        #pragma unroll
        for (int f8 = 0; f8 < 4; f8++) {
            const int n = warp_n * 32 + f8 * 8 + 2 * tq;
            float2 bv = *(const float2*)&b2[n];
            int rl = warp_m * 32 + fm * 16 + quad;
            *(float2*)&h3_s[rl * 128 + n] =
                {geluf(acc[fm][f8][0] + bv.x), geluf(acc[fm][f8][1] + bv.y)};
            *(float2*)&h3_s[(rl + 8) * 128 + n] =
                {geluf(acc[fm][f8][2] + bv.x), geluf(acc[fm][f8][3] + bv.y)};
        }
    }
    __syncthreads();

    const int d0 = lane * 4;
    float4 wv[7];
    #pragma unroll
    for (int j = 0; j < 7; j++) wv[j] = *(const float4*)&w3p[j * 128 + d0];
    #pragma unroll 1
    for (int rr = 0; rr < 8; rr++) {
        int row = wid * 8 + rr;
        float4 h = *(const float4*)&h3_s[row * 128 + d0];
        float r[7];
        #pragma unroll
        for (int j = 0; j < 7; j++) {
            float p = h.x * wv[j].x + h.y * wv[j].y + h.z * wv[j].z + h.w * wv[j].w;
            r[j] = wsum(p);
        }
        if (lane == 0) {
            #pragma unroll
            for (int j = 0; j < 7; j++)
                outp[(size_t)(m0 + row) * 7 + j] = r[j] + b3p[j];
        }
    }
}

// ---------------------------------------------------------------------------
extern "C" void kernel_launch(void* const* d_in, const int* in_sizes, int n_in,
                              void* d_out, int out_size)
{
    const float* f_swin    = (const float*)d_in[0];
    const float* f_maxvit  = (const float*)d_in[1];
    const float* f_focal   = (const float*)d_in[2];
    const float* in_proj_w = (const float*)d_in[3];
    const float* in_proj_b = (const float*)d_in[4];
    const float* out_w  = (const float*)d_in[5];
    const float* out_b  = (const float*)d_in[6];
    const float* ln1_g  = (const float*)d_in[7];
    const float* ln1_b  = (const float*)d_in[8];
    const float* gate_w = (const float*)d_in[9];
    const float* gate_b = (const float*)d_in[10];
    const float* ln2_g  = (const float*)d_in[11];
    const float* ln2_b  = (const float*)d_in[12];
    const float* w1 = (const float*)d_in[13];
    const float* b1 = (const float*)d_in[14];
    const float* w2 = (const float*)d_in[15];
    const float* b2 = (const float*)d_in[16];
    const float* w3 = (const float*)d_in[17];
    const float* b3 = (const float*)d_in[18];

    int B = in_sizes[0] / 256;
    if (B > BMAX) B = BMAX;
    int rows3 = 3 * B;

    float* outp = (float*)d_out;
    float* out_logits = outp;
    float* out_fused = (out_size >= B * 263) ? (outp + (size_t)B * 7) : nullptr;

    const int SMEM_QA = 24576 + 32768 + 36864 + 12288 + 128;   // 106624 (occ 2)
    const int SMEM_DH = 16384 + 32768 + 65536 + 128;           // 114816 (occ 2)
    cudaFuncSetAttribute(qkv_attn_out, cudaFuncAttributeMaxDynamicSharedMemorySize, SMEM_QA);
    cudaFuncSetAttribute(deephead, cudaFuncAttributeMaxDynamicSharedMemorySize, SMEM_DH);

    dim3 blk(256);

    conv_w_all<<<352, blk>>>(in_proj_w, out_w, w1, w2);
    // fused qkv + attention + out-proj (occ 2)
    qkv_attn_out<<<rows3 / 48, blk, SMEM_QA>>>(in_proj_b, out_b,
                                               f_swin, f_maxvit, f_focal);
    // residual + LN1 + gate + fused + LN2
    fuse_k<<<2048, blk>>>(f_swin, f_maxvit, f_focal,
                          ln1_g, ln1_b, gate_w, gate_b, ln2_g, ln2_b,
                          out_fused, B);
    // deep head fused (occ 2)
    deephead<<<B / 64, blk, SMEM_DH>>>(b1, b2, w3, b3, out_logits);
}

// round 12
// speedup vs baseline: 1.2399x; 1.2399x over previous
#include <cuda_runtime.h>
#include <cuda_bf16.h>
#include <math.h>
#include <stdint.h>

typedef unsigned int u32;
typedef unsigned long long u64;

#define BMAX 65536

// ---------------------------------------------------------------------------
// Device scratch.
//  g_att : attention out (pre-residual) bf16 [3B, 256]
//  g_hh  : LN2(fused) split bf16             [B, 512]  (hi | lo)
//  g_w   : split weights                     [rows, 512]
// ---------------------------------------------------------------------------
__device__ __nv_bfloat16 g_att[(size_t)BMAX * 3 * 256];
__device__ __nv_bfloat16 g_hh [(size_t)BMAX * 512];
__device__ __nv_bfloat16 g_w  [(size_t)(768 + 256 + 256 + 128) * 512];

#define WOFF_QKV 0
#define WOFF_OUT (768 * 512)
#define WOFF_W1  ((768 + 256) * 512)
#define WOFF_W2  ((768 + 512) * 512)

__device__ __forceinline__ u32 smem_u32(const void* p) {
    u32 a;
    asm("{ .reg .u64 t; cvta.to.shared.u64 t, %1; cvt.u32.u64 %0, t; }" : "=r"(a) : "l"(p));
    return a;
}
__device__ __forceinline__ float geluf(float x) {
    return 0.5f * x * (1.0f + erff(x * 0.7071067811865476f));
}
__device__ __forceinline__ float wsum(float v) {
    #pragma unroll
    for (int o = 16; o > 0; o >>= 1) v += __shfl_xor_sync(0xffffffffu, v, o);
    return v;
}
__device__ __forceinline__ u32 bf2bits(__nv_bfloat162 h) {
    return *reinterpret_cast<u32*>(&h);
}
__device__ __forceinline__ void split2(float a, float b, u32& h, u32& l) {
    __nv_bfloat162 hh = __floats2bfloat162_rn(a, b);
    float ra = a - __bfloat162float(hh.x);
    float rb = b - __bfloat162float(hh.y);
    __nv_bfloat162 ll = __floats2bfloat162_rn(ra, rb);
    h = bf2bits(hh);
    l = bf2bits(ll);
}

// ---------------------------------------------------------------------------
// merged weight conversion: fp32 [rows,256] -> split bf16 [rows,512]
// ---------------------------------------------------------------------------
__global__ __launch_bounds__(256)
void conv_w_all(const float* __restrict__ ipw, const float* __restrict__ ow,
                const float* __restrict__ w1, const float* __restrict__ w2)
{
    int id = blockIdx.x * 256 + threadIdx.x;
    int row = id >> 6;
    int k = (id & 63) << 2;
    const float* src; int r, woff;
    if (row < 768)       { src = ipw; r = row;        woff = WOFF_QKV; }
    else if (row < 1024) { src = ow;  r = row - 768;  woff = WOFF_OUT; }
    else if (row < 1280) { src = w1;  r = row - 1024; woff = WOFF_W1; }
    else                 { src = w2;  r = row - 1280; woff = WOFF_W2; }
    float4 v = *(const float4*)(src + (size_t)r * 256 + k);
    u32 h0, l0, h1, l1;
    split2(v.x, v.y, h0, l0);
    split2(v.z, v.w, h1, l1);
    __nv_bfloat16* dst = g_w + (size_t)woff + (size_t)r * 512;
    u32* hp = (u32*)(dst + k);
    u32* lp = (u32*)(dst + 256 + k);
    hp[0] = h0; hp[1] = h1;
    lp[0] = l0; lp[1] = l1;
}

// ---------------------------------------------------------------------------
// MMA helpers
// ---------------------------------------------------------------------------
__device__ __forceinline__ void ldsm4(u32 addr, u32& r0, u32& r1, u32& r2, u32& r3) {
    asm volatile("ldmatrix.sync.aligned.m8n8.x4.shared.b16 {%0,%1,%2,%3}, [%4];"
                 : "=r"(r0), "=r"(r1), "=r"(r2), "=r"(r3) : "r"(addr));
}
__device__ __forceinline__ void mma16816(float* c, const u32* a, u32 b0, u32 b1) {
    asm volatile(
        "mma.sync.aligned.m16n8k16.row.col.f32.bf16.bf16.f32 "
        "{%0,%1,%2,%3}, {%4,%5,%6,%7}, {%8,%9}, {%0,%1,%2,%3};"
        : "+f"(c[0]), "+f"(c[1]), "+f"(c[2]), "+f"(c[3])
        : "r"(a[0]), "r"(a[1]), "r"(a[2]), "r"(a[3]), "r"(b0), "r"(b1));
}

// load NROWS x 128B chunk into SW128-swizzled smem via cp.async
template<int NROWS, int ROWB>
__device__ __forceinline__ void load_tile(u32 sbase, const char* gb) {
    constexpr int ITERS = NROWS * 8 / 256;
    int tid = threadIdx.x;
    #pragma unroll
    for (int i = 0; i < ITERS; i++) {
        int seg = i * 256 + tid;
        int r = seg >> 3, c = seg & 7;
        u32 off = (u32)(r * 128 + c * 16);
        off ^= (off >> 3) & 0x70;
        asm volatile("cp.async.cg.shared.global [%0], [%1], 16;"
                     :: "r"(sbase + off), "l"(gb + (size_t)r * ROWB + c * 16));
    }
}

// 96-row feature chunk: fp32 -> bf16 direct into swizzled smem
__device__ __forceinline__ void load_Afeat96(u32 sbase, int m0, int c,
                                             const float* __restrict__ s0,
                                             const float* __restrict__ s1,
                                             const float* __restrict__ s2)
{
    int tid = threadIdx.x;
    #pragma unroll
    for (int i = 0; i < 3; i++) {
        int seg = i * 256 + tid;
        int r = seg >> 3, c8 = seg & 7;
        int m = m0 + r;
        int b = m / 3, t = m - 3 * b;
        const float* src = ((t == 0) ? s0 : (t == 1) ? s1 : s2)
                           + (size_t)b * 256 + c * 64 + c8 * 8;
        float4 v0 = *(const float4*)src;
        float4 v1 = *(const float4*)(src + 4);
        u32 w0 = bf2bits(__floats2bfloat162_rn(v0.x, v0.y));
        u32 w1 = bf2bits(__floats2bfloat162_rn(v0.z, v0.w));
        u32 w2 = bf2bits(__floats2bfloat162_rn(v1.x, v1.y));
        u32 w3 = bf2bits(__floats2bfloat162_rn(v1.z, v1.w));
        u32 off = (u32)(r * 128 + c8 * 16);
        off ^= (off >> 3) & 0x70;
        asm volatile("st.shared.v4.b32 [%0], {%1,%2,%3,%4};"
                     :: "r"(sbase + off), "r"(w0), "r"(w1), "r"(w2), "r"(w3));
    }
}

// ---------------------------------------------------------------------------
// qkv_attn_out: fused qkv projection + attention + out-proj.
//  M_TILE = 96 rows = 32 whole batches.
// smem: A 4x12288 (48K) | W 2x16384 (32K) | qkv 147456 (144K) = 224K
// ---------------------------------------------------------------------------
__global__ __launch_bounds__(256)
void qkv_attn_out(const float* __restrict__ ipb, const float* __restrict__ ob,
                  const float* __restrict__ s0, const float* __restrict__ s1,
                  const float* __restrict__ s2)
{
    extern __shared__ char dsm[];
    char* dbase = (char*)((((uintptr_t)dsm) + 1023) & ~(uintptr_t)1023);
    u32 base = smem_u32(dbase);
    const u32 wbase = base + 49152;
    char* qkv_s = dbase + 81920;              // [96][768] bf16, row stride 1536B

    const int tid = threadIdx.x;
    const int lane = tid & 31;
    const int wid = tid >> 5;
    const int warp_m = wid & 1;               // 0..1 -> 48 rows
    const int warp_n = wid >> 1;              // 0..3 -> 32 cols
    const int m0 = blockIdx.x * 96;

    const char* Wq = (const char*)(g_w + WOFF_QKV);
    const char* Wo = (const char*)(g_w + WOFF_OUT);

    const int a_mi = lane >> 3;
    const int a_row_base = ((a_mi & 1) << 3) + (lane & 7);
    const int a_kb_sel = (lane >> 4) << 4;
    const int b_row_base = ((a_mi >> 1) << 3) + (lane & 7);
    const int b_kb_sel = ((lane >> 3) & 1) << 4;
    const int quad = lane >> 2, tq = lane & 3;

    // ---------------- phase 1: qkv GEMM ----------------
    load_tile<128, 1024>(wbase, Wq);
    asm volatile("cp.async.commit_group;");
    #pragma unroll
    for (int c = 0; c < 4; c++)
        load_Afeat96(base + c * 12288, m0, c, s0, s1, s2);

    #pragma unroll 1
    for (int nt = 0; nt < 6; nt++) {
        float acc[3][4][4];
        #pragma unroll
        for (int i = 0; i < 3; i++)
            #pragma unroll
            for (int j = 0; j < 4; j++)
                #pragma unroll
                for (int q = 0; q < 4; q++) acc[i][j][q] = 0.f;

        #pragma unroll
        for (int kc = 0; kc < 4; kc++) {
            const int gc = nt * 4 + kc;
            if (gc + 1 < 24) {
                const int nnt = (gc + 1) >> 2, nkc = (gc + 1) & 3;
                load_tile<128, 1024>(wbase + ((gc + 1) & 1) * 16384,
                                     Wq + (size_t)nnt * 131072 + nkc * 128);
                asm volatile("cp.async.commit_group;");
                asm volatile("cp.async.wait_group 1;");
            } else {
                asm volatile("cp.async.wait_group 0;");
            }
            __syncthreads();

            const u32 As = base + kc * 12288;
            const u32 Bs = wbase + (gc & 1) * 16384;
            #pragma unroll
            for (int ks = 0; ks < 4; ks++) {
                u32 a[3][4];
                #pragma unroll
                for (int fm = 0; fm < 3; fm++) {
                    int row = warp_m * 48 + fm * 16 + a_row_base;
                    u32 kb = (u32)(ks * 32 + a_kb_sel);
                    u32 ad = As + row * 128 + (kb ^ ((row & 7) << 4));
                    ldsm4(ad, a[fm][0], a[fm][1], a[fm][2], a[fm][3]);
                }
                u32 b[2][4];
                #pragma unroll
                for (int fn = 0; fn < 2; fn++) {
                    int row = warp_n * 32 + fn * 16 + b_row_base;
                    u32 kb = (u32)(ks * 32 + b_kb_sel);
                    u32 bd = Bs + row * 128 + (kb ^ ((row & 7) << 4));
                    ldsm4(bd, b[fn][0], b[fn][1], b[fn][2], b[fn][3]);
                }
                #pragma unroll
                for (int fm = 0; fm < 3; fm++)
                    #pragma unroll
                    for (int f8 = 0; f8 < 4; f8++)
                        mma16816(acc[fm][f8], a[fm],
                                 b[f8 >> 1][(f8 & 1) * 2], b[f8 >> 1][(f8 & 1) * 2 + 1]);
            }
            __syncthreads();
        }

        // park this n-tile's qkv in smem (+bias, bf16)
        #pragma unroll
        for (int fm = 0; fm < 3; fm++) {
            const int r = warp_m * 48 + fm * 16 + quad;
            #pragma unroll
            for (int f8 = 0; f8 < 4; f8++) {
                const int ncol = nt * 128 + warp_n * 32 + f8 * 8 + 2 * tq;
                float2 bv = *(const float2*)&ipb[ncol];
                u32 lo = bf2bits(__floats2bfloat162_rn(acc[fm][f8][0] + bv.x,
                                                       acc[fm][f8][1] + bv.y));
                u32 hi = bf2bits(__floats2bfloat162_rn(acc[fm][f8][2] + bv.x,
                                                       acc[fm][f8][3] + bv.y));
                *(u32*)(qkv_s + (size_t)r * 1536 + ncol * 2)       = lo;
                *(u32*)(qkv_s + (size_t)(r + 8) * 1536 + ncol * 2) = hi;
            }
        }
    }
    __syncthreads();

    // W prologue for out-proj: overlaps attention phase
    load_tile<128, 1024>(wbase, Wo);
    asm volatile("cp.async.commit_group;");

    // ---------------- phase 2: attention; ctx -> A region ----------------
    const int d0 = lane * 8;
    const int ctx_ch = lane >> 3;
    const int ctx_inb = (d0 & 63) * 2;
    #pragma unroll 1
    for (int bl = 0; bl < 4; bl++) {
        int tb = wid * 4 + bl;

        float q[3][8], k[3][8], v[3][8];
        #pragma unroll
        for (int t = 0; t < 3; t++) {
            const char* rp = qkv_s + (size_t)(tb * 3 + t) * 1536 + d0 * 2;
            uint4 qr = *(const uint4*)rp;
            uint4 kr = *(const uint4*)(rp + 512);
            uint4 vr = *(const uint4*)(rp + 1024);
            const u32* qw = (const u32*)&qr;
            const u32* kw = (const u32*)&kr;
            const u32* vw = (const u32*)&vr;
            #pragma unroll
            for (int j = 0; j < 4; j++) {
                float2 qf = __bfloat1622float2(*(const __nv_bfloat162*)&qw[j]);
                float2 kf = __bfloat1622float2(*(const __nv_bfloat162*)&kw[j]);
                float2 vf = __bfloat1622float2(*(const __nv_bfloat162*)&vw[j]);
                q[t][2*j] = qf.x; q[t][2*j+1] = qf.y;
                k[t][2*j] = kf.x; k[t][2*j+1] = kf.y;
                v[t][2*j] = vf.x; v[t][2*j+1] = vf.y;
            }
        }
        float s[3][3];
        #pragma unroll
        for (int t = 0; t < 3; t++)
            #pragma unroll
            for (int u = 0; u < 3; u++) {
                float p = 0.f;
                #pragma unroll
                for (int j = 0; j < 8; j++) p += q[t][j] * k[u][j];
                p += __shfl_xor_sync(0xffffffffu, p, 1);
                p += __shfl_xor_sync(0xffffffffu, p, 2);
                p += __shfl_xor_sync(0xffffffffu, p, 4);
                s[t][u] = p * 0.125f;
            }
        #pragma unroll
        for (int t = 0; t < 3; t++) {
            float mx = fmaxf(s[t][0], fmaxf(s[t][1], s[t][2]));
            float e0 = expf(s[t][0] - mx);
            float e1 = expf(s[t][1] - mx);
            float e2 = expf(s[t][2] - mx);
            float inv = 1.f / (e0 + e1 + e2);
            u32 cw[4];
            #pragma unroll
            for (int j = 0; j < 8; j += 2) {
                float c0 = (e0 * v[0][j]   + e1 * v[1][j]   + e2 * v[2][j])   * inv;
                float c1 = (e0 * v[0][j+1] + e1 * v[1][j+1] + e2 * v[2][j+1]) * inv;
                cw[j >> 1] = bf2bits(__floats2bfloat162_rn(c0, c1));
            }
            int row = tb * 3 + t;
            u32 off = (u32)(row * 128 + ctx_inb);
            off ^= (off >> 3) & 0x70;
            asm volatile("st.shared.v4.b32 [%0], {%1,%2,%3,%4};"
                         :: "r"(base + ctx_ch * 12288 + off),
                            "r"(cw[0]), "r"(cw[1]), "r"(cw[2]), "r"(cw[3]));
        }
    }
    __syncthreads();

    // ---------------- phase 3: out-proj (ctx x out_w hi) -> g_att bf16 -----
    #pragma unroll 1
    for (int nt2 = 0; nt2 < 2; nt2++) {
        float acc[3][4][4];
        #pragma unroll
        for (int i = 0; i < 3; i++)
            #pragma unroll
            for (int j = 0; j < 4; j++)
                #pragma unroll
                for (int q = 0; q < 4; q++) acc[i][j][q] = 0.f;

        #pragma unroll
        for (int kc = 0; kc < 4; kc++) {
            const int gc = nt2 * 4 + kc;
            if (gc + 1 < 8) {
                load_tile<128, 1024>(wbase + ((gc + 1) & 1) * 16384,
                                     Wo + (size_t)((gc + 1) >> 2) * 131072 + ((gc + 1) & 3) * 128);
                asm volatile("cp.async.commit_group;");
                asm volatile("cp.async.wait_group 1;");
            } else {
                asm volatile("cp.async.wait_group 0;");
            }
            __syncthreads();

            const u32 As = base + kc * 12288;
            const u32 Bs = wbase + (gc & 1) * 16384;
            #pragma unroll
            for (int ks = 0; ks < 4; ks++) {
                u32 a[3][4];
                #pragma unroll
                for (int fm = 0; fm < 3; fm++) {
                    int row = warp_m * 48 + fm * 16 + a_row_base;
                    u32 kb = (u32)(ks * 32 + a_kb_sel);
                    u32 ad = As + row * 128 + (kb ^ ((row & 7) << 4));
                    ldsm4(ad, a[fm][0], a[fm][1], a[fm][2], a[fm][3]);
                }
                u32 b[2][4];
                #pragma unroll
                for (int fn = 0; fn < 2; fn++) {
                    int row = warp_n * 32 + fn * 16 + b_row_base;
                    u32 kb = (u32)(ks * 32 + b_kb_sel);
                    u32 bd = Bs + row * 128 + (kb ^ ((row & 7) << 4));
                    ldsm4(bd, b[fn][0], b[fn][1], b[fn][2], b[fn][3]);
                }
                #pragma unroll
                for (int fm = 0; fm < 3; fm++)
                    #pragma unroll
                    for (int f8 = 0; f8 < 4; f8++)
                        mma16816(acc[fm][f8], a[fm],
                                 b[f8 >> 1][(f8 & 1) * 2], b[f8 >> 1][(f8 & 1) * 2 + 1]);
            }
            __syncthreads();
        }

        #pragma unroll
        for (int fm = 0; fm < 3; fm++) {
            const int r = warp_m * 48 + fm * 16 + quad;
            #pragma unroll
            for (int f8 = 0; f8 < 4; f8++) {
                const int ncol = nt2 * 128 + warp_n * 32 + f8 * 8 + 2 * tq;
                float2 bv = *(const float2*)&ob[ncol];
                u32 lo = bf2bits(__floats2bfloat162_rn(acc[fm][f8][0] + bv.x,
                                                       acc[fm][f8][1] + bv.y));
                u32 hi = bf2bits(__floats2bfloat162_rn(acc[fm][f8][2] + bv.x,
                                                       acc[fm][f8][3] + bv.y));
                *(u32*)&g_att[(size_t)(m0 + r) * 256 + ncol]     = lo;
                *(u32*)&g_att[(size_t)(m0 + r + 8) * 256 + ncol] = hi;
            }
        }
    }
}

// ---------------------------------------------------------------------------
// fuse: x = att(bf16) + feat; LN1, gate softmax, fused (fp32), LN2 -> g_hh.
// Vectorized float4 smem reads (bank-conflict-free LDS.128).
// ---------------------------------------------------------------------------
__global__ __launch_bounds__(256)
void fuse_k(const float* __restrict__ s0, const float* __restrict__ s1,
            const float* __restrict__ s2,
            const float* __restrict__ ln1g, const float* __restrict__ ln1b,
            const float* __restrict__ gw,   const float* __restrict__ gb,
            const float* __restrict__ ln2g, const float* __restrict__ ln2b,
            float* __restrict__ out_fused, int B)
{
    __shared__ float s_gw[2304];
    __shared__ float s_ln[1024];
    for (int i = threadIdx.x; i < 2304; i += 256) s_gw[i] = gw[i];
    if (threadIdx.x < 256) {
        int i = threadIdx.x;
        s_ln[i]       = ln1g[i];
        s_ln[256 + i] = ln1b[i];
        s_ln[512 + i] = ln2g[i];
        s_ln[768 + i] = ln2b[i];
    }
    __syncthreads();

    int warp = threadIdx.x >> 5, lane = threadIdx.x & 31;
    int d0 = lane * 8;
    const float* srcs[3] = {s0, s1, s2};

    float g1v[8], b1v[8], g2v[8], b2v[8];
    *(float4*)&g1v[0] = *(const float4*)&s_ln[d0];
    *(float4*)&g1v[4] = *(const float4*)&s_ln[d0 + 4];
    *(float4*)&b1v[0] = *(const float4*)&s_ln[256 + d0];
    *(float4*)&b1v[4] = *(const float4*)&s_ln[256 + d0 + 4];
    *(float4*)&g2v[0] = *(const float4*)&s_ln[512 + d0];
    *(float4*)&g2v[4] = *(const float4*)&s_ln[512 + d0 + 4];
    *(float4*)&b2v[0] = *(const float4*)&s_ln[768 + d0];
    *(float4*)&b2v[4] = *(const float4*)&s_ln[768 + d0 + 4];

    for (int b = blockIdx.x * 8 + warp; b < B; b += gridDim.x * 8) {
        float y[3][8];
        float gpart[3] = {0.f, 0.f, 0.f};
        #pragma unroll
        for (int t = 0; t < 3; t++) {
            float iv[8];
            const float* in = srcs[t] + (size_t)b * 256;
            *(float4*)&iv[0] = *(const float4*)(in + d0);
            *(float4*)&iv[4] = *(const float4*)(in + d0 + 4);
            float x[8];
            uint4 ar = *(const uint4*)(g_att + ((size_t)b * 3 + t) * 256 + d0);
            const u32* aw = (const u32*)&ar;
            #pragma unroll
            for (int j = 0; j < 4; j++) {
                float2 af = __bfloat1622float2(*(const __nv_bfloat162*)&aw[j]);
                x[2*j]   = af.x + iv[2*j];
                x[2*j+1] = af.y + iv[2*j+1];
            }
            float s = 0.f;
            #pragma unroll
            for (int j = 0; j < 8; j++) s += x[j];
            s = wsum(s);
            float mu = s * (1.f / 256.f);
            float vv = 0.f;
            #pragma unroll
            for (int j = 0; j < 8; j++) { float d = x[j] - mu; vv += d * d; }
            vv = wsum(vv);
            float rs = rsqrtf(vv * (1.f / 256.f) + 1e-5f);
            #pragma unroll
            for (int j = 0; j < 8; j++)
                y[t][j] = (x[j] - mu) * rs * g1v[j] + b1v[j];

            #pragma unroll
            for (int g = 0; g < 3; g++) {
                float4 wa = *(const float4*)&s_gw[g * 768 + t * 256 + d0];
                float4 wb = *(const float4*)&s_gw[g * 768 + t * 256 + d0 + 4];
                gpart[g] += iv[0] * wa.x + iv[1] * wa.y + iv[2] * wa.z + iv[3] * wa.w
                          + iv[4] * wb.x + iv[5] * wb.y + iv[6] * wb.z + iv[7] * wb.w;
            }
        }
        float gl[3];
        #pragma unroll
        for (int g = 0; g < 3; g++) gl[g] = wsum(gpart[g]) + gb[g];
        float mx = fmaxf(gl[0], fmaxf(gl[1], gl[2]));
        float e0 = expf(gl[0] - mx), e1 = expf(gl[1] - mx), e2 = expf(gl[2] - mx);
        float inv = 1.f / (e0 + e1 + e2);
        float w0 = e0 * inv, w1 = e1 * inv, w2 = e2 * inv;

        float f[8];
        #pragma unroll
        for (int j = 0; j < 8; j++)
            f[j] = w0 * y[0][j] + w1 * y[1][j] + w2 * y[2][j];
        if (out_fused) {
            float* orow = out_fused + (size_t)b * 256 + d0;
            *(float4*)orow       = *(float4*)&f[0];
            *(float4*)(orow + 4) = *(float4*)&f[4];
        }
        float s2v = 0.f;
        #pragma unroll
        for (int j = 0; j < 8; j++) s2v += f[j];
        s2v = wsum(s2v);
        float mu2 = s2v * (1.f / 256.f);
        float vv2 = 0.f;
        #pragma unroll
        for (int j = 0; j < 8; j++) { float d = f[j] - mu2; vv2 += d * d; }
        vv2 = wsum(vv2);
        float rs2 = rsqrtf(vv2 * (1.f / 256.f) + 1e-5f);
        u32 hi[4], lo[4];
        #pragma unroll
        for (int j = 0; j < 8; j += 2) {
            float h0 = (f[j]   - mu2) * rs2 * g2v[j]   + b2v[j];
            float h1 = (f[j+1] - mu2) * rs2 * g2v[j+1] + b2v[j+1];
            split2(h0, h1, hi[j >> 1], lo[j >> 1]);
        }
        __nv_bfloat16* hrow = g_hh + (size_t)b * 512 + d0;
        *(uint4*)hrow         = *(uint4*)hi;
        *(uint4*)(hrow + 256) = *(uint4*)lo;
    }
}

// ---------------------------------------------------------------------------
// deephead (occ-2): M_TILE=64, A streamed (2x8K), W streamed (2x16K),
// H2 resident (8x8K = 64K). Total 112K -> 2 CTAs/SM.
// Chunk indices computed arithmetically (no local-memory arrays).
// ---------------------------------------------------------------------------
__device__ __forceinline__ int a_idx12f(int kc) { return (kc < 8) ? (kc & 3) : (kc - 4); }
__device__ __forceinline__ int w_idx12f(int kc) { return (kc < 8) ? kc : (kc - 8); }

__global__ __launch_bounds__(256, 2)
void deephead(const float* __restrict__ b1, const float* __restrict__ b2,
              const float* __restrict__ w3p, const float* __restrict__ b3p,
              float* __restrict__ outp)
{
    extern __shared__ char dsm[];
    char* dbase = (char*)((((uintptr_t)dsm) + 127) & ~(uintptr_t)127);
    u32 base = smem_u32(dbase);
    const u32 abase = base;              // 2 x 8192
    const u32 wbase = base + 16384;      // 2 x 16384
    const u32 hbase = base + 49152;      // 8 x 8192

    const int tid = threadIdx.x;
    const int lane = tid & 31;
    const int wid = tid >> 5;
    const int warp_m = wid & 1;
    const int warp_n = wid >> 1;
    const int m0 = blockIdx.x * 64;

    const char* Ab  = (const char*)g_hh + (size_t)m0 * 1024;
    const char* W1b = (const char*)(g_w + WOFF_W1);
    const char* W2b = (const char*)(g_w + WOFF_W2);

    const int a_mi = lane >> 3;
    const int a_row_base = ((a_mi & 1) << 3) + (lane & 7);
    const int a_kb_sel = (lane >> 4) << 4;
    const int b_row_base = ((a_mi >> 1) << 3) + (lane & 7);
    const int b_kb_sel = ((lane >> 3) & 1) << 4;
    const int quad = lane >> 2, tq = lane & 3;

    float acc[2][4][4];
    #pragma unroll
    for (int i = 0; i < 2; i++)
        #pragma unroll
        for (int j = 0; j < 4; j++)
            #pragma unroll
            for (int q = 0; q < 4; q++) acc[i][j][q] = 0.f;

    load_tile<64, 1024>(abase, Ab);
    load_tile<128, 1024>(wbase, W1b);
    asm volatile("cp.async.commit_group;");

    // ---------------- phase 1: h2 = GELU(hh @ w1^T + b1) --------------------
    #pragma unroll 1
    for (int g = 0; g < 24; g++) {
        const int nt = g / 12, kc = g - nt * 12;
        if (g < 23) {
            const int g1 = g + 1;
            const int nt1 = g1 / 12, kc1 = g1 - nt1 * 12;
            load_tile<64, 1024>(abase + (g1 & 1) * 8192, Ab + a_idx12f(kc1) * 128);
            load_tile<128, 1024>(wbase + (g1 & 1) * 16384,
                                 W1b + (size_t)nt1 * 131072 + w_idx12f(kc1) * 128);
        } else {
            load_tile<128, 1024>(wbase, W2b);
        }
        asm volatile("cp.async.commit_group;");
        asm volatile("cp.async.wait_group 1;");
        __syncthreads();

        const u32 As = abase + (g & 1) * 8192;
        const u32 Bs = wbase + (g & 1) * 16384;
        #pragma unroll
        for (int ks = 0; ks < 4; ks++) {
            u32 a[2][4];
            #pragma unroll
            for (int fm = 0; fm < 2; fm++) {
                int row = warp_m * 32 + fm * 16 + a_row_base;
                u32 kb = (u32)(ks * 32 + a_kb_sel);
                u32 ad = As + row * 128 + (kb ^ ((row & 7) << 4));
                ldsm4(ad, a[fm][0], a[fm][1], a[fm][2], a[fm][3]);
            }
            u32 b[2][4];
            #pragma unroll
            for (int fn = 0; fn < 2; fn++) {
                int row = warp_n * 32 + fn * 16 + b_row_base;
                u32 kb = (u32)(ks * 32 + b_kb_sel);
                u32 bd = Bs + row * 128 + (kb ^ ((row & 7) << 4));
                ldsm4(bd, b[fn][0], b[fn][1], b[fn][2], b[fn][3]);
            }
            #pragma unroll
            for (int fm = 0; fm < 2; fm++)
                #pragma unroll
                for (int f8 = 0; f8 < 4; f8++)
                    mma16816(acc[fm][f8], a[fm],
                             b[f8 >> 1][(f8 & 1) * 2], b[f8 >> 1][(f8 & 1) * 2 + 1]);
        }
        __syncthreads();

        if (kc == 11) {
            #pragma unroll
            for (int fm = 0; fm < 2; fm++) {
                #pragma unroll
                for (int f8 = 0; f8 < 4; f8++) {
                    const int ncol = nt * 128 + warp_n * 32 + f8 * 8 + 2 * tq;
                    float2 bv = *(const float2*)&b1[ncol];
                    float v0 = geluf(acc[fm][f8][0] + bv.x);
                    float v1 = geluf(acc[fm][f8][1] + bv.y);
                    float v2 = geluf(acc[fm][f8][2] + bv.x);
                    float v3 = geluf(acc[fm][f8][3] + bv.y);
                    u32 h0, l0, h1, l1;
                    split2(v0, v1, h0, l0);
                    split2(v2, v3, h1, l1);
                    const int chl = ncol >> 6;
                    const u32 hi_slot = hbase + chl * 8192;
                    const u32 lo_slot = hbase + 32768 + chl * 8192;
                    const int bb = (ncol & 63) * 2;
                    const int r0 = warp_m * 32 + fm * 16 + quad;
                    #pragma unroll
                    for (int wh = 0; wh < 2; wh++) {
                        int row = r0 + wh * 8;
                        u32 off = (u32)(row * 128 + (bb & ~15));
                        off ^= (off >> 3) & 0x70;
                        off += (u32)(bb & 15);
                        u32 hv = wh ? h1 : h0;
                        u32 lv = wh ? l1 : l0;
                        asm volatile("st.shared.b32 [%0], %1;" :: "r"(hi_slot + off), "r"(hv));
                        asm volatile("st.shared.b32 [%0], %1;" :: "r"(lo_slot + off), "r"(lv));
                    }
                    acc[fm][f8][0] = 0.f; acc[fm][f8][1] = 0.f;
                    acc[fm][f8][2] = 0.f; acc[fm][f8][3] = 0.f;
                }
            }
        }
    }

    // ---------------- phase 2: h3 = GELU(h2 @ w2^T + b2) --------------------
    #pragma unroll 1
    for (int j = 0; j < 12; j++) {
        if (j < 11) {
            load_tile<128, 1024>(wbase + ((25 + j) & 1) * 16384,
                                 W2b + w_idx12f(j + 1) * 128);
            asm volatile("cp.async.commit_group;");
            asm volatile("cp.async.wait_group 1;");
        } else {
            asm volatile("cp.async.wait_group 0;");
        }
        __syncthreads();

        const u32 As = hbase + a_idx12f(j) * 8192;
        const u32 Bs = wbase + ((24 + j) & 1) * 16384;
        #pragma unroll
        for (int ks = 0; ks < 4; ks++) {
            u32 a[2][4];
            #pragma unroll
            for (int fm = 0; fm < 2; fm++) {
                int row = warp_m * 32 + fm * 16 + a_row_base;
                u32 kb = (u32)(ks * 32 + a_kb_sel);
                u32 ad = As + row * 128 + (kb ^ ((row & 7) << 4));
                ldsm4(ad, a[fm][0], a[fm][1], a[fm][2], a[fm][3]);
            }
            u32 b[2][4];
            #pragma unroll
            for (int fn = 0; fn < 2; fn++) {
                int row = warp_n * 32 + fn * 16 + b_row_base;
                u32 kb = (u32)(ks * 32 + b_kb_sel);
                u32 bd = Bs + row * 128 + (kb ^ ((row & 7) << 4));
                ldsm4(bd, b[fn][0], b[fn][1], b[fn][2], b[fn][3]);
            }
            #pragma unroll
            for (int fm = 0; fm < 2; fm++)
                #pragma unroll
                for (int f8 = 0; f8 < 4; f8++)
                    mma16816(acc[fm][f8], a[fm],
                             b[f8 >> 1][(f8 & 1) * 2], b[f8 >> 1][(f8 & 1) * 2 + 1]);
        }
        __syncthreads();
    }

    float* h3_s = (float*)(dbase + 49152);
    #pragma unroll
    for (int fm = 0; fm < 2; fm++) {
        #pragma unroll
        for (int f8 = 0; f8 < 4; f8++) {
            const int n = warp_n * 32 + f8 * 8 + 2 * tq;
            float2 bv = *(const float2*)&b2[n];
            int rl = warp_m * 32 + fm * 16 + quad;
            *(float2*)&h3_s[rl * 128 + n] =
                {geluf(acc[fm][f8][0] + bv.x), geluf(acc[fm][f8][1] + bv.y)};
            *(float2*)&h3_s[(rl + 8) * 128 + n] =
                {geluf(acc[fm][f8][2] + bv.x), geluf(acc[fm][f8][3] + bv.y)};
        }
    }
    __syncthreads();

    const int d0 = lane * 4;
    float4 wv[7];
    #pragma unroll
    for (int j = 0; j < 7; j++) wv[j] = *(const float4*)&w3p[j * 128 + d0];
    #pragma unroll 1
    for (int rr = 0; rr < 8; rr++) {
        int row = wid * 8 + rr;
        float4 h = *(const float4*)&h3_s[row * 128 + d0];
        float r[7];
        #pragma unroll
        for (int j = 0; j < 7; j++) {
            float p = h.x * wv[j].x + h.y * wv[j].y + h.z * wv[j].z + h.w * wv[j].w;
            r[j] = wsum(p);
        }
        if (lane == 0) {
            #pragma unroll
            for (int j = 0; j < 7; j++)
                outp[(size_t)(m0 + row) * 7 + j] = r[j] + b3p[j];
        }
    }
}

// ---------------------------------------------------------------------------
extern "C" void kernel_launch(void* const* d_in, const int* in_sizes, int n_in,
                              void* d_out, int out_size)
{
    const float* f_swin    = (const float*)d_in[0];
    const float* f_maxvit  = (const float*)d_in[1];
    const float* f_focal   = (const float*)d_in[2];
    const float* in_proj_w = (const float*)d_in[3];
    const float* in_proj_b = (const float*)d_in[4];
    const float* out_w  = (const float*)d_in[5];
    const float* out_b  = (const float*)d_in[6];
    const float* ln1_g  = (const float*)d_in[7];
    const float* ln1_b  = (const float*)d_in[8];
    const float* gate_w = (const float*)d_in[9];
    const float* gate_b = (const float*)d_in[10];
    const float* ln2_g  = (const float*)d_in[11];
    const float* ln2_b  = (const float*)d_in[12];
    const float* w1 = (const float*)d_in[13];
    const float* b1 = (const float*)d_in[14];
    const float* w2 = (const float*)d_in[15];
    const float* b2 = (const float*)d_in[16];
    const float* w3 = (const float*)d_in[17];
    const float* b3 = (const float*)d_in[18];

    int B = in_sizes[0] / 256;
    if (B > BMAX) B = BMAX;
    int rows3 = 3 * B;

    float* outp = (float*)d_out;
    float* out_logits = outp;
    float* out_fused = (out_size >= B * 263) ? (outp + (size_t)B * 7) : nullptr;

    const int SMEM_QA = 49152 + 32768 + 147456 + 1024;   // 230400 (occ 1)
    const int SMEM_DH = 16384 + 32768 + 65536 + 128;     // 114816 (occ 2)
    cudaFuncSetAttribute(qkv_attn_out, cudaFuncAttributeMaxDynamicSharedMemorySize, SMEM_QA);
    cudaFuncSetAttribute(deephead, cudaFuncAttributeMaxDynamicSharedMemorySize, SMEM_DH);

    dim3 blk(256);

    conv_w_all<<<352, blk>>>(in_proj_w, out_w, w1, w2);
    // fused qkv + attention + out-proj (M_TILE=96, occ 1 — verified best)
    qkv_attn_out<<<rows3 / 96, blk, SMEM_QA>>>(in_proj_b, out_b,
                                               f_swin, f_maxvit, f_focal);
    // residual + LN1 + gate + fused + LN2
    fuse_k<<<2048, blk>>>(f_swin, f_maxvit, f_focal,
                          ln1_g, ln1_b, gate_w, gate_b, ln2_g, ln2_b,
                          out_fused, B);
    // deep head fused (occ 2)
    deephead<<<B / 64, blk, SMEM_DH>>>(b1, b2, w3, b3, out_logits);
}

// round 13
// speedup vs baseline: 1.2803x; 1.0326x over previous
#include <cuda_runtime.h>
#include <cuda_bf16.h>
#include <math.h>
#include <stdint.h>

typedef unsigned int u32;
typedef unsigned long long u64;

#define BMAX 65536

// ---------------------------------------------------------------------------
// Device scratch.
//  g_att : attention out (pre-residual) bf16 [3B, 256]
//  g_hh  : LN2(fused) split bf16             [B, 512]  (hi | lo)
//  g_w   : split weights                     [rows, 512]
// ---------------------------------------------------------------------------
__device__ __nv_bfloat16 g_att[(size_t)BMAX * 3 * 256];
__device__ __nv_bfloat16 g_hh [(size_t)BMAX * 512];
__device__ __nv_bfloat16 g_w  [(size_t)(768 + 256 + 256 + 128) * 512];

#define WOFF_QKV 0
#define WOFF_OUT (768 * 512)
#define WOFF_W1  ((768 + 256) * 512)
#define WOFF_W2  ((768 + 512) * 512)

__device__ __forceinline__ u32 smem_u32(const void* p) {
    u32 a;
    asm("{ .reg .u64 t; cvta.to.shared.u64 t, %1; cvt.u32.u64 %0, t; }" : "=r"(a) : "l"(p));
    return a;
}
__device__ __forceinline__ float geluf(float x) {
    return 0.5f * x * (1.0f + erff(x * 0.7071067811865476f));
}
__device__ __forceinline__ float wsum(float v) {
    #pragma unroll
    for (int o = 16; o > 0; o >>= 1) v += __shfl_xor_sync(0xffffffffu, v, o);
    return v;
}
__device__ __forceinline__ u32 bf2bits(__nv_bfloat162 h) {
    return *reinterpret_cast<u32*>(&h);
}
__device__ __forceinline__ void split2(float a, float b, u32& h, u32& l) {
    __nv_bfloat162 hh = __floats2bfloat162_rn(a, b);
    float ra = a - __bfloat162float(hh.x);
    float rb = b - __bfloat162float(hh.y);
    __nv_bfloat162 ll = __floats2bfloat162_rn(ra, rb);
    h = bf2bits(hh);
    l = bf2bits(ll);
}

// ---------------------------------------------------------------------------
// merged weight conversion: fp32 [rows,256] -> split bf16 [rows,512]
// ---------------------------------------------------------------------------
__global__ __launch_bounds__(256)
void conv_w_all(const float* __restrict__ ipw, const float* __restrict__ ow,
                const float* __restrict__ w1, const float* __restrict__ w2)
{
    int id = blockIdx.x * 256 + threadIdx.x;
    int row = id >> 6;
    int k = (id & 63) << 2;
    const float* src; int r, woff;
    if (row < 768)       { src = ipw; r = row;        woff = WOFF_QKV; }
    else if (row < 1024) { src = ow;  r = row - 768;  woff = WOFF_OUT; }
    else if (row < 1280) { src = w1;  r = row - 1024; woff = WOFF_W1; }
    else                 { src = w2;  r = row - 1280; woff = WOFF_W2; }
    float4 v = *(const float4*)(src + (size_t)r * 256 + k);
    u32 h0, l0, h1, l1;
    split2(v.x, v.y, h0, l0);
    split2(v.z, v.w, h1, l1);
    __nv_bfloat16* dst = g_w + (size_t)woff + (size_t)r * 512;
    u32* hp = (u32*)(dst + k);
    u32* lp = (u32*)(dst + 256 + k);
    hp[0] = h0; hp[1] = h1;
    lp[0] = l0; lp[1] = l1;
}

// ---------------------------------------------------------------------------
// MMA helpers
// ---------------------------------------------------------------------------
__device__ __forceinline__ void ldsm4(u32 addr, u32& r0, u32& r1, u32& r2, u32& r3) {
    asm volatile("ldmatrix.sync.aligned.m8n8.x4.shared.b16 {%0,%1,%2,%3}, [%4];"
                 : "=r"(r0), "=r"(r1), "=r"(r2), "=r"(r3) : "r"(addr));
}
__device__ __forceinline__ void mma16816(float* c, const u32* a, u32 b0, u32 b1) {
    asm volatile(
        "mma.sync.aligned.m16n8k16.row.col.f32.bf16.bf16.f32 "
        "{%0,%1,%2,%3}, {%4,%5,%6,%7}, {%8,%9}, {%0,%1,%2,%3};"
        : "+f"(c[0]), "+f"(c[1]), "+f"(c[2]), "+f"(c[3])
        : "r"(a[0]), "r"(a[1]), "r"(a[2]), "r"(a[3]), "r"(b0), "r"(b1));
}

// load NROWS x 128B chunk into SW128-swizzled smem via cp.async
template<int NROWS, int ROWB>
__device__ __forceinline__ void load_tile(u32 sbase, const char* gb) {
    constexpr int ITERS = NROWS * 8 / 256;
    int tid = threadIdx.x;
    #pragma unroll
    for (int i = 0; i < ITERS; i++) {
        int seg = i * 256 + tid;
        int r = seg >> 3, c = seg & 7;
        u32 off = (u32)(r * 128 + c * 16);
        off ^= (off >> 3) & 0x70;
        asm volatile("cp.async.cg.shared.global [%0], [%1], 16;"
                     :: "r"(sbase + off), "l"(gb + (size_t)r * ROWB + c * 16));
    }
}

// 96-row feature chunk: fp32 -> bf16 direct into swizzled smem
__device__ __forceinline__ void load_Afeat96(u32 sbase, int m0, int c,
                                             const float* __restrict__ s0,
                                             const float* __restrict__ s1,
                                             const float* __restrict__ s2)
{
    int tid = threadIdx.x;
    #pragma unroll
    for (int i = 0; i < 3; i++) {
        int seg = i * 256 + tid;
        int r = seg >> 3, c8 = seg & 7;
        int m = m0 + r;
        int b = m / 3, t = m - 3 * b;
        const float* src = ((t == 0) ? s0 : (t == 1) ? s1 : s2)
                           + (size_t)b * 256 + c * 64 + c8 * 8;
        float4 v0 = *(const float4*)src;
        float4 v1 = *(const float4*)(src + 4);
        u32 w0 = bf2bits(__floats2bfloat162_rn(v0.x, v0.y));
        u32 w1 = bf2bits(__floats2bfloat162_rn(v0.z, v0.w));
        u32 w2 = bf2bits(__floats2bfloat162_rn(v1.x, v1.y));
        u32 w3 = bf2bits(__floats2bfloat162_rn(v1.z, v1.w));
        u32 off = (u32)(r * 128 + c8 * 16);
        off ^= (off >> 3) & 0x70;
        asm volatile("st.shared.v4.b32 [%0], {%1,%2,%3,%4};"
                     :: "r"(sbase + off), "r"(w0), "r"(w1), "r"(w2), "r"(w3));
    }
}

// ---------------------------------------------------------------------------
// qkv_attn_out: fused qkv projection + attention + out-proj.
//  M_TILE = 96 rows = 32 whole batches. Single-sync double-buffered pipeline:
//  per chunk: wait_group 0; sync; issue load(g+1); MMA(g).
// smem: A 4x12288 (48K) | W 2x16384 (32K) | qkv 147456 (144K) = 224K
// ---------------------------------------------------------------------------
__global__ __launch_bounds__(256)
void qkv_attn_out(const float* __restrict__ ipb, const float* __restrict__ ob,
                  const float* __restrict__ s0, const float* __restrict__ s1,
                  const float* __restrict__ s2)
{
    extern __shared__ char dsm[];
    char* dbase = (char*)((((uintptr_t)dsm) + 1023) & ~(uintptr_t)1023);
    u32 base = smem_u32(dbase);
    const u32 wbase = base + 49152;
    char* qkv_s = dbase + 81920;              // [96][768] bf16, row stride 1536B

    const int tid = threadIdx.x;
    const int lane = tid & 31;
    const int wid = tid >> 5;
    const int warp_m = wid & 1;               // 0..1 -> 48 rows
    const int warp_n = wid >> 1;              // 0..3 -> 32 cols
    const int m0 = blockIdx.x * 96;

    const char* Wq = (const char*)(g_w + WOFF_QKV);
    const char* Wo = (const char*)(g_w + WOFF_OUT);

    const int a_mi = lane >> 3;
    const int a_row_base = ((a_mi & 1) << 3) + (lane & 7);
    const int a_kb_sel = (lane >> 4) << 4;
    const int b_row_base = ((a_mi >> 1) << 3) + (lane & 7);
    const int b_kb_sel = ((lane >> 3) & 1) << 4;
    const int quad = lane >> 2, tq = lane & 3;

    // ---------------- phase 1: qkv GEMM ----------------
    load_tile<128, 1024>(wbase, Wq);          // chunk 0
    asm volatile("cp.async.commit_group;");
    #pragma unroll
    for (int c = 0; c < 4; c++)
        load_Afeat96(base + c * 12288, m0, c, s0, s1, s2);

    #pragma unroll 1
    for (int nt = 0; nt < 6; nt++) {
        float acc[3][4][4];
        #pragma unroll
        for (int i = 0; i < 3; i++)
            #pragma unroll
            for (int j = 0; j < 4; j++)
                #pragma unroll
                for (int q = 0; q < 4; q++) acc[i][j][q] = 0.f;

        #pragma unroll
        for (int kc = 0; kc < 4; kc++) {
            const int gc = nt * 4 + kc;
            asm volatile("cp.async.wait_group 0;");
            __syncthreads();
            if (gc + 1 < 24) {
                const int nnt = (gc + 1) >> 2, nkc = (gc + 1) & 3;
                load_tile<128, 1024>(wbase + ((gc + 1) & 1) * 16384,
                                     Wq + (size_t)nnt * 131072 + nkc * 128);
                asm volatile("cp.async.commit_group;");
            } else {
                // prefetch out-proj W chunk 0 (into buffer (24&1)=0)
                load_tile<128, 1024>(wbase, Wo);
                asm volatile("cp.async.commit_group;");
            }

            const u32 As = base + kc * 12288;
            const u32 Bs = wbase + (gc & 1) * 16384;
            #pragma unroll
            for (int ks = 0; ks < 4; ks++) {
                u32 a[3][4];
                #pragma unroll
                for (int fm = 0; fm < 3; fm++) {
                    int row = warp_m * 48 + fm * 16 + a_row_base;
                    u32 kb = (u32)(ks * 32 + a_kb_sel);
                    u32 ad = As + row * 128 + (kb ^ ((row & 7) << 4));
                    ldsm4(ad, a[fm][0], a[fm][1], a[fm][2], a[fm][3]);
                }
                u32 b[2][4];
                #pragma unroll
                for (int fn = 0; fn < 2; fn++) {
                    int row = warp_n * 32 + fn * 16 + b_row_base;
                    u32 kb = (u32)(ks * 32 + b_kb_sel);
                    u32 bd = Bs + row * 128 + (kb ^ ((row & 7) << 4));
                    ldsm4(bd, b[fn][0], b[fn][1], b[fn][2], b[fn][3]);
                }
                #pragma unroll
                for (int fm = 0; fm < 3; fm++)
                    #pragma unroll
                    for (int f8 = 0; f8 < 4; f8++)
                        mma16816(acc[fm][f8], a[fm],
                                 b[f8 >> 1][(f8 & 1) * 2], b[f8 >> 1][(f8 & 1) * 2 + 1]);
            }
        }

        // park this n-tile's qkv in smem (+bias, bf16); qkv_s not read until
        // the sync after phase 1 + attention-phase sync, so no barrier here.
        #pragma unroll
        for (int fm = 0; fm < 3; fm++) {
            const int r = warp_m * 48 + fm * 16 + quad;
            #pragma unroll
            for (int f8 = 0; f8 < 4; f8++) {
                const int ncol = nt * 128 + warp_n * 32 + f8 * 8 + 2 * tq;
                float2 bv = *(const float2*)&ipb[ncol];
                u32 lo = bf2bits(__floats2bfloat162_rn(acc[fm][f8][0] + bv.x,
                                                       acc[fm][f8][1] + bv.y));
                u32 hi = bf2bits(__floats2bfloat162_rn(acc[fm][f8][2] + bv.x,
                                                       acc[fm][f8][3] + bv.y));
                *(u32*)(qkv_s + (size_t)r * 1536 + ncol * 2)       = lo;
                *(u32*)(qkv_s + (size_t)(r + 8) * 1536 + ncol * 2) = hi;
            }
        }
    }
    __syncthreads();      // qkv_s fully parked; Wo chunk 0 in flight

    // ---------------- phase 2: attention; ctx -> A region ----------------
    const int d0 = lane * 8;
    const int ctx_ch = lane >> 3;
    const int ctx_inb = (d0 & 63) * 2;
    #pragma unroll 1
    for (int bl = 0; bl < 4; bl++) {
        int tb = wid * 4 + bl;

        float q[3][8], k[3][8], v[3][8];
        #pragma unroll
        for (int t = 0; t < 3; t++) {
            const char* rp = qkv_s + (size_t)(tb * 3 + t) * 1536 + d0 * 2;
            uint4 qr = *(const uint4*)rp;
            uint4 kr = *(const uint4*)(rp + 512);
            uint4 vr = *(const uint4*)(rp + 1024);
            const u32* qw = (const u32*)&qr;
            const u32* kw = (const u32*)&kr;
            const u32* vw = (const u32*)&vr;
            #pragma unroll
            for (int j = 0; j < 4; j++) {
                float2 qf = __bfloat1622float2(*(const __nv_bfloat162*)&qw[j]);
                float2 kf = __bfloat1622float2(*(const __nv_bfloat162*)&kw[j]);
                float2 vf = __bfloat1622float2(*(const __nv_bfloat162*)&vw[j]);
                q[t][2*j] = qf.x; q[t][2*j+1] = qf.y;
                k[t][2*j] = kf.x; k[t][2*j+1] = kf.y;
                v[t][2*j] = vf.x; v[t][2*j+1] = vf.y;
            }
        }
        float s[3][3];
        #pragma unroll
        for (int t = 0; t < 3; t++)
            #pragma unroll
            for (int u = 0; u < 3; u++) {
                float p = 0.f;
                #pragma unroll
                for (int j = 0; j < 8; j++) p += q[t][j] * k[u][j];
                p += __shfl_xor_sync(0xffffffffu, p, 1);
                p += __shfl_xor_sync(0xffffffffu, p, 2);
                p += __shfl_xor_sync(0xffffffffu, p, 4);
                s[t][u] = p * 0.125f;
            }
        #pragma unroll
        for (int t = 0; t < 3; t++) {
            float mx = fmaxf(s[t][0], fmaxf(s[t][1], s[t][2]));
            float e0 = expf(s[t][0] - mx);
            float e1 = expf(s[t][1] - mx);
            float e2 = expf(s[t][2] - mx);
            float inv = 1.f / (e0 + e1 + e2);
            u32 cw[4];
            #pragma unroll
            for (int j = 0; j < 8; j += 2) {
                float c0 = (e0 * v[0][j]   + e1 * v[1][j]   + e2 * v[2][j])   * inv;
                float c1 = (e0 * v[0][j+1] + e1 * v[1][j+1] + e2 * v[2][j+1]) * inv;
                cw[j >> 1] = bf2bits(__floats2bfloat162_rn(c0, c1));
            }
            int row = tb * 3 + t;
            u32 off = (u32)(row * 128 + ctx_inb);
            off ^= (off >> 3) & 0x70;
            asm volatile("st.shared.v4.b32 [%0], {%1,%2,%3,%4};"
                         :: "r"(base + ctx_ch * 12288 + off),
                            "r"(cw[0]), "r"(cw[1]), "r"(cw[2]), "r"(cw[3]));
        }
    }

    // ---------------- phase 3: out-proj (ctx x out_w hi) -> g_att bf16 -----
    #pragma unroll 1
    for (int nt2 = 0; nt2 < 2; nt2++) {
        float acc[3][4][4];
        #pragma unroll
        for (int i = 0; i < 3; i++)
            #pragma unroll
            for (int j = 0; j < 4; j++)
                #pragma unroll
                for (int q = 0; q < 4; q++) acc[i][j][q] = 0.f;

        #pragma unroll
        for (int kc = 0; kc < 4; kc++) {
            const int gc = nt2 * 4 + kc;
            asm volatile("cp.async.wait_group 0;");
            __syncthreads();   // chunk gc ready; ctx writes published (gc==0)
            if (gc + 1 < 8) {
                load_tile<128, 1024>(wbase + ((gc + 1) & 1) * 16384,
                                     Wo + (size_t)((gc + 1) >> 2) * 131072 + ((gc + 1) & 3) * 128);
                asm volatile("cp.async.commit_group;");
            }

            const u32 As = base + kc * 12288;
            const u32 Bs = wbase + (gc & 1) * 16384;
            #pragma unroll
            for (int ks = 0; ks < 4; ks++) {
                u32 a[3][4];
                #pragma unroll
                for (int fm = 0; fm < 3; fm++) {
                    int row = warp_m * 48 + fm * 16 + a_row_base;
                    u32 kb = (u32)(ks * 32 + a_kb_sel);
                    u32 ad = As + row * 128 + (kb ^ ((row & 7) << 4));
                    ldsm4(ad, a[fm][0], a[fm][1], a[fm][2], a[fm][3]);
                }
                u32 b[2][4];
                #pragma unroll
                for (int fn = 0; fn < 2; fn++) {
                    int row = warp_n * 32 + fn * 16 + b_row_base;
                    u32 kb = (u32)(ks * 32 + b_kb_sel);
                    u32 bd = Bs + row * 128 + (kb ^ ((row & 7) << 4));
                    ldsm4(bd, b[fn][0], b[fn][1], b[fn][2], b[fn][3]);
                }
                #pragma unroll
                for (int fm = 0; fm < 3; fm++)
                    #pragma unroll
                    for (int f8 = 0; f8 < 4; f8++)
                        mma16816(acc[fm][f8], a[fm],
                                 b[f8 >> 1][(f8 & 1) * 2], b[f8 >> 1][(f8 & 1) * 2 + 1]);
            }
        }

        #pragma unroll
        for (int fm = 0; fm < 3; fm++) {
            const int r = warp_m * 48 + fm * 16 + quad;
            #pragma unroll
            for (int f8 = 0; f8 < 4; f8++) {
                const int ncol = nt2 * 128 + warp_n * 32 + f8 * 8 + 2 * tq;
                float2 bv = *(const float2*)&ob[ncol];
                u32 lo = bf2bits(__floats2bfloat162_rn(acc[fm][f8][0] + bv.x,
                                                       acc[fm][f8][1] + bv.y));
                u32 hi = bf2bits(__floats2bfloat162_rn(acc[fm][f8][2] + bv.x,
                                                       acc[fm][f8][3] + bv.y));
                *(u32*)&g_att[(size_t)(m0 + r) * 256 + ncol]     = lo;
                *(u32*)&g_att[(size_t)(m0 + r + 8) * 256 + ncol] = hi;
            }
        }
    }
}

// ---------------------------------------------------------------------------
// fuse: x = att(bf16) + feat; LN1, gate softmax, fused (fp32), LN2 -> g_hh.
// (reverted to R10 smem-scalar form — R12 register-caching was neutral/negative)
// ---------------------------------------------------------------------------
__global__ __launch_bounds__(256)
void fuse_k(const float* __restrict__ s0, const float* __restrict__ s1,
            const float* __restrict__ s2,
            const float* __restrict__ ln1g, const float* __restrict__ ln1b,
            const float* __restrict__ gw,   const float* __restrict__ gb,
            const float* __restrict__ ln2g, const float* __restrict__ ln2b,
            float* __restrict__ out_fused, int B)
{
    __shared__ float s_gw[2304];
    __shared__ float s_ln[1024];
    for (int i = threadIdx.x; i < 2304; i += 256) s_gw[i] = gw[i];
    if (threadIdx.x < 256) {
        int i = threadIdx.x;
        s_ln[i]       = ln1g[i];
        s_ln[256 + i] = ln1b[i];
        s_ln[512 + i] = ln2g[i];
        s_ln[768 + i] = ln2b[i];
    }
    __syncthreads();

    int warp = threadIdx.x >> 5, lane = threadIdx.x & 31;
    int d0 = lane * 8;
    const float* srcs[3] = {s0, s1, s2};

    for (int b = blockIdx.x * 8 + warp; b < B; b += gridDim.x * 8) {
        float y[3][8];
        float gpart[3] = {0.f, 0.f, 0.f};
        #pragma unroll
        for (int t = 0; t < 3; t++) {
            float iv[8];
            const float* in = srcs[t] + (size_t)b * 256;
            *(float4*)&iv[0] = *(const float4*)(in + d0);
            *(float4*)&iv[4] = *(const float4*)(in + d0 + 4);
            float x[8];
            uint4 ar = *(const uint4*)(g_att + ((size_t)b * 3 + t) * 256 + d0);
            const u32* aw = (const u32*)&ar;
            #pragma unroll
            for (int j = 0; j < 4; j++) {
                float2 af = __bfloat1622float2(*(const __nv_bfloat162*)&aw[j]);
                x[2*j]   = af.x + iv[2*j];
                x[2*j+1] = af.y + iv[2*j+1];
            }
            float s = 0.f;
            #pragma unroll
            for (int j = 0; j < 8; j++) s += x[j];
            s = wsum(s);
            float mu = s * (1.f / 256.f);
            float vv = 0.f;
            #pragma unroll
            for (int j = 0; j < 8; j++) { float d = x[j] - mu; vv += d * d; }
            vv = wsum(vv);
            float rs = rsqrtf(vv * (1.f / 256.f) + 1e-5f);
            #pragma unroll
            for (int j = 0; j < 8; j++)
                y[t][j] = (x[j] - mu) * rs * s_ln[d0 + j] + s_ln[256 + d0 + j];

            #pragma unroll
            for (int g = 0; g < 3; g++) {
                const float* wrow = s_gw + g * 768 + t * 256 + d0;
                #pragma unroll
                for (int j = 0; j < 8; j++) gpart[g] += iv[j] * wrow[j];
            }
        }
        float gl[3];
        #pragma unroll
        for (int g = 0; g < 3; g++) gl[g] = wsum(gpart[g]) + gb[g];
        float mx = fmaxf(gl[0], fmaxf(gl[1], gl[2]));
        float e0 = expf(gl[0] - mx), e1 = expf(gl[1] - mx), e2 = expf(gl[2] - mx);
        float inv = 1.f / (e0 + e1 + e2);
        float w0 = e0 * inv, w1 = e1 * inv, w2 = e2 * inv;

        float f[8];
        #pragma unroll
        for (int j = 0; j < 8; j++)
            f[j] = w0 * y[0][j] + w1 * y[1][j] + w2 * y[2][j];
        if (out_fused) {
            float* orow = out_fused + (size_t)b * 256 + d0;
            *(float4*)orow       = *(float4*)&f[0];
            *(float4*)(orow + 4) = *(float4*)&f[4];
        }
        float s2v = 0.f;
        #pragma unroll
        for (int j = 0; j < 8; j++) s2v += f[j];
        s2v = wsum(s2v);
        float mu2 = s2v * (1.f / 256.f);
        float vv2 = 0.f;
        #pragma unroll
        for (int j = 0; j < 8; j++) { float d = f[j] - mu2; vv2 += d * d; }
        vv2 = wsum(vv2);
        float rs2 = rsqrtf(vv2 * (1.f / 256.f) + 1e-5f);
        u32 hi[4], lo[4];
        #pragma unroll
        for (int j = 0; j < 8; j += 2) {
            float h0 = (f[j]   - mu2) * rs2 * s_ln[512 + d0 + j]   + s_ln[768 + d0 + j];
            float h1 = (f[j+1] - mu2) * rs2 * s_ln[512 + d0 + j+1] + s_ln[768 + d0 + j+1];
            split2(h0, h1, hi[j >> 1], lo[j >> 1]);
        }
        __nv_bfloat16* hrow = g_hh + (size_t)b * 512 + d0;
        *(uint4*)hrow         = *(uint4*)hi;
        *(uint4*)(hrow + 256) = *(uint4*)lo;
    }
}

// ---------------------------------------------------------------------------
// deephead (occ-2): M_TILE=64, single-sync pipeline, arithmetic chunk indices.
// smem: A 2x8K | W 2x16K | H2 8x8K = 112K -> 2 CTAs/SM.
// ---------------------------------------------------------------------------
__device__ __forceinline__ int a_idx12f(int kc) { return (kc < 8) ? (kc & 3) : (kc - 4); }
__device__ __forceinline__ int w_idx12f(int kc) { return (kc < 8) ? kc : (kc - 8); }

__global__ __launch_bounds__(256, 2)
void deephead(const float* __restrict__ b1, const float* __restrict__ b2,
              const float* __restrict__ w3p, const float* __restrict__ b3p,
              float* __restrict__ outp)
{
    extern __shared__ char dsm[];
    char* dbase = (char*)((((uintptr_t)dsm) + 127) & ~(uintptr_t)127);
    u32 base = smem_u32(dbase);
    const u32 abase = base;              // 2 x 8192
    const u32 wbase = base + 16384;      // 2 x 16384
    const u32 hbase = base + 49152;      // 8 x 8192

    const int tid = threadIdx.x;
    const int lane = tid & 31;
    const int wid = tid >> 5;
    const int warp_m = wid & 1;
    const int warp_n = wid >> 1;
    const int m0 = blockIdx.x * 64;

    const char* Ab  = (const char*)g_hh + (size_t)m0 * 1024;
    const char* W1b = (const char*)(g_w + WOFF_W1);
    const char* W2b = (const char*)(g_w + WOFF_W2);

    const int a_mi = lane >> 3;
    const int a_row_base = ((a_mi & 1) << 3) + (lane & 7);
    const int a_kb_sel = (lane >> 4) << 4;
    const int b_row_base = ((a_mi >> 1) << 3) + (lane & 7);
    const int b_kb_sel = ((lane >> 3) & 1) << 4;
    const int quad = lane >> 2, tq = lane & 3;

    float acc[2][4][4];
    #pragma unroll
    for (int i = 0; i < 2; i++)
        #pragma unroll
        for (int j = 0; j < 4; j++)
            #pragma unroll
            for (int q = 0; q < 4; q++) acc[i][j][q] = 0.f;

    load_tile<64, 1024>(abase, Ab);
    load_tile<128, 1024>(wbase, W1b);
    asm volatile("cp.async.commit_group;");

    // ---------------- phase 1: h2 = GELU(hh @ w1^T + b1) --------------------
    #pragma unroll 1
    for (int g = 0; g < 24; g++) {
        const int nt = g / 12, kc = g - nt * 12;
        asm volatile("cp.async.wait_group 0;");
        __syncthreads();
        if (g < 23) {
            const int g1 = g + 1;
            const int nt1 = g1 / 12, kc1 = g1 - nt1 * 12;
            load_tile<64, 1024>(abase + (g1 & 1) * 8192, Ab + a_idx12f(kc1) * 128);
            load_tile<128, 1024>(wbase + (g1 & 1) * 16384,
                                 W1b + (size_t)nt1 * 131072 + w_idx12f(kc1) * 128);
            asm volatile("cp.async.commit_group;");
        } else {
            load_tile<128, 1024>(wbase, W2b);
            asm volatile("cp.async.commit_group;");
        }

        const u32 As = abase + (g & 1) * 8192;
        const u32 Bs = wbase + (g & 1) * 16384;
        #pragma unroll
        for (int ks = 0; ks < 4; ks++) {
            u32 a[2][4];
            #pragma unroll
            for (int fm = 0; fm < 2; fm++) {
                int row = warp_m * 32 + fm * 16 + a_row_base;
                u32 kb = (u32)(ks * 32 + a_kb_sel);
                u32 ad = As + row * 128 + (kb ^ ((row & 7) << 4));
                ldsm4(ad, a[fm][0], a[fm][1], a[fm][2], a[fm][3]);
            }
            u32 b[2][4];
            #pragma unroll
            for (int fn = 0; fn < 2; fn++) {
                int row = warp_n * 32 + fn * 16 + b_row_base;
                u32 kb = (u32)(ks * 32 + b_kb_sel);
                u32 bd = Bs + row * 128 + (kb ^ ((row & 7) << 4));
                ldsm4(bd, b[fn][0], b[fn][1], b[fn][2], b[fn][3]);
            }
            #pragma unroll
            for (int fm = 0; fm < 2; fm++)
                #pragma unroll
                for (int f8 = 0; f8 < 4; f8++)
                    mma16816(acc[fm][f8], a[fm],
                             b[f8 >> 1][(f8 & 1) * 2], b[f8 >> 1][(f8 & 1) * 2 + 1]);
        }

        if (kc == 11) {
            // H2 slots written here are first read in phase 2 (after syncs).
            #pragma unroll
            for (int fm = 0; fm < 2; fm++) {
                #pragma unroll
                for (int f8 = 0; f8 < 4; f8++) {
                    const int ncol = nt * 128 + warp_n * 32 + f8 * 8 + 2 * tq;
                    float2 bv = *(const float2*)&b1[ncol];
                    float v0 = geluf(acc[fm][f8][0] + bv.x);
                    float v1 = geluf(acc[fm][f8][1] + bv.y);
                    float v2 = geluf(acc[fm][f8][2] + bv.x);
                    float v3 = geluf(acc[fm][f8][3] + bv.y);
                    u32 h0, l0, h1, l1;
                    split2(v0, v1, h0, l0);
                    split2(v2, v3, h1, l1);
                    const int chl = ncol >> 6;
                    const u32 hi_slot = hbase + chl * 8192;
                    const u32 lo_slot = hbase + 32768 + chl * 8192;
                    const int bb = (ncol & 63) * 2;
                    const int r0 = warp_m * 32 + fm * 16 + quad;
                    #pragma unroll
                    for (int wh = 0; wh < 2; wh++) {
                        int row = r0 + wh * 8;
                        u32 off = (u32)(row * 128 + (bb & ~15));
                        off ^= (off >> 3) & 0x70;
                        off += (u32)(bb & 15);
                        u32 hv = wh ? h1 : h0;
                        u32 lv = wh ? l1 : l0;
                        asm volatile("st.shared.b32 [%0], %1;" :: "r"(hi_slot + off), "r"(hv));
                        asm volatile("st.shared.b32 [%0], %1;" :: "r"(lo_slot + off), "r"(lv));
                    }
                    acc[fm][f8][0] = 0.f; acc[fm][f8][1] = 0.f;
                    acc[fm][f8][2] = 0.f; acc[fm][f8][3] = 0.f;
                }
            }
        }
    }

    // ---------------- phase 2: h3 = GELU(h2 @ w2^T + b2) --------------------
    #pragma unroll 1
    for (int j = 0; j < 12; j++) {
        asm volatile("cp.async.wait_group 0;");
        __syncthreads();       // W2 chunk j ready; H2 writes published (j==0)
        if (j < 11) {
            load_tile<128, 1024>(wbase + ((25 + j) & 1) * 16384,
                                 W2b + w_idx12f(j + 1) * 128);
            asm volatile("cp.async.commit_group;");
        }

        const u32 As = hbase + a_idx12f(j) * 8192;
        const u32 Bs = wbase + ((24 + j) & 1) * 16384;
        #pragma unroll
        for (int ks = 0; ks < 4; ks++) {
            u32 a[2][4];
            #pragma unroll
            for (int fm = 0; fm < 2; fm++) {
                int row = warp_m * 32 + fm * 16 + a_row_base;
                u32 kb = (u32)(ks * 32 + a_kb_sel);
                u32 ad = As + row * 128 + (kb ^ ((row & 7) << 4));
                ldsm4(ad, a[fm][0], a[fm][1], a[fm][2], a[fm][3]);
            }
            u32 b[2][4];
            #pragma unroll
            for (int fn = 0; fn < 2; fn++) {
                int row = warp_n * 32 + fn * 16 + b_row_base;
                u32 kb = (u32)(ks * 32 + b_kb_sel);
                u32 bd = Bs + row * 128 + (kb ^ ((row & 7) << 4));
                ldsm4(bd, b[fn][0], b[fn][1], b[fn][2], b[fn][3]);
            }
            #pragma unroll
            for (int fm = 0; fm < 2; fm++)
                #pragma unroll
                for (int f8 = 0; f8 < 4; f8++)
                    mma16816(acc[fm][f8], a[fm],
                             b[f8 >> 1][(f8 & 1) * 2], b[f8 >> 1][(f8 & 1) * 2 + 1]);
        }
    }
    __syncthreads();   // all MMA reads of H2 done before overwriting with h3

    float* h3_s = (float*)(dbase + 49152);
    #pragma unroll
    for (int fm = 0; fm < 2; fm++) {
        #pragma unroll
        for (int f8 = 0; f8 < 4; f8++) {
            const int n = warp_n * 32 + f8 * 8 + 2 * tq;
            float2 bv = *(const float2*)&b2[n];
            int rl = warp_m * 32 + fm * 16 + quad;
            *(float2*)&h3_s[rl * 128 + n] =
                {geluf(acc[fm][f8][0] + bv.x), geluf(acc[fm][f8][1] + bv.y)};
            *(float2*)&h3_s[(rl + 8) * 128 + n] =
                {geluf(acc[fm][f8][2] + bv.x), geluf(acc[fm][f8][3] + bv.y)};
        }
    }
    __syncthreads();

    const int d0 = lane * 4;
    float4 wv[7];
    #pragma unroll
    for (int j = 0; j < 7; j++) wv[j] = *(const float4*)&w3p[j * 128 + d0];
    #pragma unroll 1
    for (int rr = 0; rr < 8; rr++) {
        int row = wid * 8 + rr;
        float4 h = *(const float4*)&h3_s[row * 128 + d0];
        float r[7];
        #pragma unroll
        for (int j = 0; j < 7; j++) {
            float p = h.x * wv[j].x + h.y * wv[j].y + h.z * wv[j].z + h.w * wv[j].w;
            r[j] = wsum(p);
        }
        if (lane == 0) {
            #pragma unroll
            for (int j = 0; j < 7; j++)
                outp[(size_t)(m0 + row) * 7 + j] = r[j] + b3p[j];
        }
    }
}

// ---------------------------------------------------------------------------
extern "C" void kernel_launch(void* const* d_in, const int* in_sizes, int n_in,
                              void* d_out, int out_size)
{
    const float* f_swin    = (const float*)d_in[0];
    const float* f_maxvit  = (const float*)d_in[1];
    const float* f_focal   = (const float*)d_in[2];
    const float* in_proj_w = (const float*)d_in[3];
    const float* in_proj_b = (const float*)d_in[4];
    const float* out_w  = (const float*)d_in[5];
    const float* out_b  = (const float*)d_in[6];
    const float* ln1_g  = (const float*)d_in[7];
    const float* ln1_b  = (const float*)d_in[8];
    const float* gate_w = (const float*)d_in[9];
    const float* gate_b = (const float*)d_in[10];
    const float* ln2_g  = (const float*)d_in[11];
    const float* ln2_b  = (const float*)d_in[12];
    const float* w1 = (const float*)d_in[13];
    const float* b1 = (const float*)d_in[14];
    const float* w2 = (const float*)d_in[15];
    const float* b2 = (const float*)d_in[16];
    const float* w3 = (const float*)d_in[17];
    const float* b3 = (const float*)d_in[18];

    int B = in_sizes[0] / 256;
    if (B > BMAX) B = BMAX;
    int rows3 = 3 * B;

    float* outp = (float*)d_out;
    float* out_logits = outp;
    float* out_fused = (out_size >= B * 263) ? (outp + (size_t)B * 7) : nullptr;

    const int SMEM_QA = 49152 + 32768 + 147456 + 1024;   // 230400 (occ 1)
    const int SMEM_DH = 16384 + 32768 + 65536 + 128;     // 114816 (occ 2)
    cudaFuncSetAttribute(qkv_attn_out, cudaFuncAttributeMaxDynamicSharedMemorySize, SMEM_QA);
    cudaFuncSetAttribute(deephead, cudaFuncAttributeMaxDynamicSharedMemorySize, SMEM_DH);

    dim3 blk(256);

    conv_w_all<<<352, blk>>>(in_proj_w, out_w, w1, w2);
    // fused qkv + attention + out-proj (M_TILE=96, occ 1, single-sync pipeline)
    qkv_attn_out<<<rows3 / 96, blk, SMEM_QA>>>(in_proj_b, out_b,
                                               f_swin, f_maxvit, f_focal);
    // residual + LN1 + gate + fused + LN2
    fuse_k<<<2048, blk>>>(f_swin, f_maxvit, f_focal,
                          ln1_g, ln1_b, gate_w, gate_b, ln2_g, ln2_b,
                          out_fused, B);
    // deep head fused (occ 2, single-sync pipeline)
    deephead<<<B / 64, blk, SMEM_DH>>>(b1, b2, w3, b3, out_logits);
}

// round 16
// speedup vs baseline: 1.3767x; 1.0752x over previous
#include <cuda_runtime.h>
#include <cuda_bf16.h>
#include <math.h>
#include <stdint.h>

typedef unsigned int u32;
typedef unsigned long long u64;

#define BMAX 65536
#define QKV_STRIDE 1552   // 16B-aligned; 388 words % 32 = 4 -> quads on 8 banks

// ---------------------------------------------------------------------------
// Device scratch.
//  g_att : attention out (pre-residual) bf16 [3B, 256]
//  g_hh  : LN2(fused) split bf16             [B, 512]  (hi | lo)
//  g_w   : split weights                     [rows, 512]
// ---------------------------------------------------------------------------
__device__ __nv_bfloat16 g_att[(size_t)BMAX * 3 * 256];
__device__ __nv_bfloat16 g_hh [(size_t)BMAX * 512];
__device__ __nv_bfloat16 g_w  [(size_t)(768 + 256 + 256 + 128) * 512];

#define WOFF_QKV 0
#define WOFF_OUT (768 * 512)
#define WOFF_W1  ((768 + 256) * 512)
#define WOFF_W2  ((768 + 512) * 512)

__device__ __forceinline__ u32 smem_u32(const void* p) {
    u32 a;
    asm("{ .reg .u64 t; cvta.to.shared.u64 t, %1; cvt.u32.u64 %0, t; }" : "=r"(a) : "l"(p));
    return a;
}
__device__ __forceinline__ float geluf(float x) {
    return 0.5f * x * (1.0f + erff(x * 0.7071067811865476f));
}
__device__ __forceinline__ float wsum(float v) {
    #pragma unroll
    for (int o = 16; o > 0; o >>= 1) v += __shfl_xor_sync(0xffffffffu, v, o);
    return v;
}
__device__ __forceinline__ u32 bf2bits(__nv_bfloat162 h) {
    return *reinterpret_cast<u32*>(&h);
}
__device__ __forceinline__ void split2(float a, float b, u32& h, u32& l) {
    __nv_bfloat162 hh = __floats2bfloat162_rn(a, b);
    float ra = a - __bfloat162float(hh.x);
    float rb = b - __bfloat162float(hh.y);
    __nv_bfloat162 ll = __floats2bfloat162_rn(ra, rb);
    h = bf2bits(hh);
    l = bf2bits(ll);
}

// ---------------------------------------------------------------------------
// merged weight conversion: fp32 [rows,256] -> split bf16 [rows,512]
// ---------------------------------------------------------------------------
__global__ __launch_bounds__(256)
void conv_w_all(const float* __restrict__ ipw, const float* __restrict__ ow,
                const float* __restrict__ w1, const float* __restrict__ w2)
{
    int id = blockIdx.x * 256 + threadIdx.x;
    int row = id >> 6;
    int k = (id & 63) << 2;
    const float* src; int r, woff;
    if (row < 768)       { src = ipw; r = row;        woff = WOFF_QKV; }
    else if (row < 1024) { src = ow;  r = row - 768;  woff = WOFF_OUT; }
    else if (row < 1280) { src = w1;  r = row - 1024; woff = WOFF_W1; }
    else                 { src = w2;  r = row - 1280; woff = WOFF_W2; }
    float4 v = *(const float4*)(src + (size_t)r * 256 + k);
    u32 h0, l0, h1, l1;
    split2(v.x, v.y, h0, l0);
    split2(v.z, v.w, h1, l1);
    __nv_bfloat16* dst = g_w + (size_t)woff + (size_t)r * 512;
    u32* hp = (u32*)(dst + k);
    u32* lp = (u32*)(dst + 256 + k);
    hp[0] = h0; hp[1] = h1;
    lp[0] = l0; lp[1] = l1;
}

// ---------------------------------------------------------------------------
// MMA helpers
// ---------------------------------------------------------------------------
__device__ __forceinline__ void ldsm4(u32 addr, u32& r0, u32& r1, u32& r2, u32& r3) {
    asm volatile("ldmatrix.sync.aligned.m8n8.x4.shared.b16 {%0,%1,%2,%3}, [%4];"
                 : "=r"(r0), "=r"(r1), "=r"(r2), "=r"(r3) : "r"(addr));
}
__device__ __forceinline__ void mma16816(float* c, const u32* a, u32 b0, u32 b1) {
    asm volatile(
        "mma.sync.aligned.m16n8k16.row.col.f32.bf16.bf16.f32 "
        "{%0,%1,%2,%3}, {%4,%5,%6,%7}, {%8,%9}, {%0,%1,%2,%3};"
        : "+f"(c[0]), "+f"(c[1]), "+f"(c[2]), "+f"(c[3])
        : "r"(a[0]), "r"(a[1]), "r"(a[2]), "r"(a[3]), "r"(b0), "r"(b1));
}

// load NROWS x 128B chunk into SW128-swizzled smem via cp.async
template<int NROWS, int ROWB>
__device__ __forceinline__ void load_tile(u32 sbase, const char* gb) {
    constexpr int ITERS = NROWS * 8 / 256;
    int tid = threadIdx.x;
    #pragma unroll
    for (int i = 0; i < ITERS; i++) {
        int seg = i * 256 + tid;
        int r = seg >> 3, c = seg & 7;
        u32 off = (u32)(r * 128 + c * 16);
        off ^= (off >> 3) & 0x70;
        asm volatile("cp.async.cg.shared.global [%0], [%1], 16;"
                     :: "r"(sbase + off), "l"(gb + (size_t)r * ROWB + c * 16));
    }
}

// 96-row feature chunk: fp32 -> bf16 direct into swizzled smem
__device__ __forceinline__ void load_Afeat96(u32 sbase, int m0, int c,
                                             const float* __restrict__ s0,
                                             const float* __restrict__ s1,
                                             const float* __restrict__ s2)
{
    int tid = threadIdx.x;
    #pragma unroll
    for (int i = 0; i < 3; i++) {
        int seg = i * 256 + tid;
        int r = seg >> 3, c8 = seg & 7;
        int m = m0 + r;
        int b = m / 3, t = m - 3 * b;
        const float* src = ((t == 0) ? s0 : (t == 1) ? s1 : s2)
                           + (size_t)b * 256 + c * 64 + c8 * 8;
        float4 v0 = *(const float4*)src;
        float4 v1 = *(const float4*)(src + 4);
        u32 w0 = bf2bits(__floats2bfloat162_rn(v0.x, v0.y));
        u32 w1 = bf2bits(__floats2bfloat162_rn(v0.z, v0.w));
        u32 w2 = bf2bits(__floats2bfloat162_rn(v1.x, v1.y));
        u32 w3 = bf2bits(__floats2bfloat162_rn(v1.z, v1.w));
        u32 off = (u32)(r * 128 + c8 * 16);
        off ^= (off >> 3) & 0x70;
        asm volatile("st.shared.v4.b32 [%0], {%1,%2,%3,%4};"
                     :: "r"(sbase + off), "r"(w0), "r"(w1), "r"(w2), "r"(w3));
    }
}

// ---------------------------------------------------------------------------
// qkv_attn_out: fused qkv projection + attention + out-proj.
//  M_TILE = 96 rows = 32 whole batches. Single-sync double-buffered pipeline:
//  per chunk: wait_group 0; sync; issue load(g+1); MMA(g).   (R13-verified)
// smem: A 4x12288 (48K) | W 2x16384 (32K) | qkv 96x1552 (145.5K) ~ 226.5K
// ---------------------------------------------------------------------------
__global__ __launch_bounds__(256)
void qkv_attn_out(const float* __restrict__ ipb, const float* __restrict__ ob,
                  const float* __restrict__ s0, const float* __restrict__ s1,
                  const float* __restrict__ s2)
{
    extern __shared__ char dsm[];
    char* dbase = (char*)((((uintptr_t)dsm) + 1023) & ~(uintptr_t)1023);
    u32 base = smem_u32(dbase);
    const u32 wbase = base + 49152;
    char* qkv_s = dbase + 81920;              // [96][768] bf16, row stride 1552B

    const int tid = threadIdx.x;
    const int lane = tid & 31;
    const int wid = tid >> 5;
    const int warp_m = wid & 1;               // 0..1 -> 48 rows
    const int warp_n = wid >> 1;              // 0..3 -> 32 cols
    const int m0 = blockIdx.x * 96;

    const char* Wq = (const char*)(g_w + WOFF_QKV);
    const char* Wo = (const char*)(g_w + WOFF_OUT);

    const int a_mi = lane >> 3;
    const int a_row_base = ((a_mi & 1) << 3) + (lane & 7);
    const int a_kb_sel = (lane >> 4) << 4;
    const int b_row_base = ((a_mi >> 1) << 3) + (lane & 7);
    const int b_kb_sel = ((lane >> 3) & 1) << 4;
    const int quad = lane >> 2, tq = lane & 3;

    // ---------------- phase 1: qkv GEMM ----------------
    load_tile<128, 1024>(wbase, Wq);          // chunk 0
    asm volatile("cp.async.commit_group;");
    #pragma unroll
    for (int c = 0; c < 4; c++)
        load_Afeat96(base + c * 12288, m0, c, s0, s1, s2);

    #pragma unroll 1
    for (int nt = 0; nt < 6; nt++) {
        float acc[3][4][4];
        #pragma unroll
        for (int i = 0; i < 3; i++)
            #pragma unroll
            for (int j = 0; j < 4; j++)
                #pragma unroll
                for (int q = 0; q < 4; q++) acc[i][j][q] = 0.f;

        #pragma unroll
        for (int kc = 0; kc < 4; kc++) {
            const int gc = nt * 4 + kc;
            asm volatile("cp.async.wait_group 0;");
            __syncthreads();
            if (gc + 1 < 24) {
                const int nnt = (gc + 1) >> 2, nkc = (gc + 1) & 3;
                load_tile<128, 1024>(wbase + ((gc + 1) & 1) * 16384,
                                     Wq + (size_t)nnt * 131072 + nkc * 128);
                asm volatile("cp.async.commit_group;");
            } else {
                // prefetch out-proj W chunk 0 (into buffer (24&1)=0)
                load_tile<128, 1024>(wbase, Wo);
                asm volatile("cp.async.commit_group;");
            }

            const u32 As = base + kc * 12288;
            const u32 Bs = wbase + (gc & 1) * 16384;
            #pragma unroll
            for (int ks = 0; ks < 4; ks++) {
                u32 a[3][4];
                #pragma unroll
                for (int fm = 0; fm < 3; fm++) {
                    int row = warp_m * 48 + fm * 16 + a_row_base;
                    u32 kb = (u32)(ks * 32 + a_kb_sel);
                    u32 ad = As + row * 128 + (kb ^ ((row & 7) << 4));
                    ldsm4(ad, a[fm][0], a[fm][1], a[fm][2], a[fm][3]);
                }
                u32 b[2][4];
                #pragma unroll
                for (int fn = 0; fn < 2; fn++) {
                    int row = warp_n * 32 + fn * 16 + b_row_base;
                    u32 kb = (u32)(ks * 32 + b_kb_sel);
                    u32 bd = Bs + row * 128 + (kb ^ ((row & 7) << 4));
                    ldsm4(bd, b[fn][0], b[fn][1], b[fn][2], b[fn][3]);
                }
                #pragma unroll
                for (int fm = 0; fm < 3; fm++)
                    #pragma unroll
                    for (int f8 = 0; f8 < 4; f8++)
                        mma16816(acc[fm][f8], a[fm],
                                 b[f8 >> 1][(f8 & 1) * 2], b[f8 >> 1][(f8 & 1) * 2 + 1]);
            }
        }

        // park this n-tile's qkv in smem (+bias, bf16); qkv_s not read until
        // the sync after phase 1, so no barrier needed here.
        #pragma unroll
        for (int fm = 0; fm < 3; fm++) {
            const int r = warp_m * 48 + fm * 16 + quad;
            #pragma unroll
            for (int f8 = 0; f8 < 4; f8++) {
                const int ncol = nt * 128 + warp_n * 32 + f8 * 8 + 2 * tq;
                float2 bv = *(const float2*)&ipb[ncol];
                u32 lo = bf2bits(__floats2bfloat162_rn(acc[fm][f8][0] + bv.x,
                                                       acc[fm][f8][1] + bv.y));
                u32 hi = bf2bits(__floats2bfloat162_rn(acc[fm][f8][2] + bv.x,
                                                       acc[fm][f8][3] + bv.y));
                *(u32*)(qkv_s + (size_t)r * QKV_STRIDE + ncol * 2)       = lo;
                *(u32*)(qkv_s + (size_t)(r + 8) * QKV_STRIDE + ncol * 2) = hi;
            }
        }
    }
    __syncthreads();      // qkv_s fully parked; Wo chunk 0 in flight

    // ---------------- phase 2: attention; ctx -> A region ----------------
    const int d0 = lane * 8;
    const int ctx_ch = lane >> 3;
    const int ctx_inb = (d0 & 63) * 2;
    #pragma unroll 1
    for (int bl = 0; bl < 4; bl++) {
        int tb = wid * 4 + bl;

        float q[3][8], k[3][8], v[3][8];
        #pragma unroll
        for (int t = 0; t < 3; t++) {
            const char* rp = qkv_s + (size_t)(tb * 3 + t) * QKV_STRIDE + d0 * 2;
            uint4 qr = *(const uint4*)rp;
            uint4 kr = *(const uint4*)(rp + 512);
            uint4 vr = *(const uint4*)(rp + 1024);
            const u32* qw = (const u32*)&qr;
            const u32* kw = (const u32*)&kr;
            const u32* vw = (const u32*)&vr;
            #pragma unroll
            for (int j = 0; j < 4; j++) {
                float2 qf = __bfloat1622float2(*(const __nv_bfloat162*)&qw[j]);
                float2 kf = __bfloat1622float2(*(const __nv_bfloat162*)&kw[j]);
                float2 vf = __bfloat1622float2(*(const __nv_bfloat162*)&vw[j]);
                q[t][2*j] = qf.x; q[t][2*j+1] = qf.y;
                k[t][2*j] = kf.x; k[t][2*j+1] = kf.y;
                v[t][2*j] = vf.x; v[t][2*j+1] = vf.y;
            }
        }
        float s[3][3];
        #pragma unroll
        for (int t = 0; t < 3; t++)
            #pragma unroll
            for (int u = 0; u < 3; u++) {
                float p = 0.f;
                #pragma unroll
                for (int j = 0; j < 8; j++) p += q[t][j] * k[u][j];
                p += __shfl_xor_sync(0xffffffffu, p, 1);
                p += __shfl_xor_sync(0xffffffffu, p, 2);
                p += __shfl_xor_sync(0xffffffffu, p, 4);
                s[t][u] = p * 0.125f;
            }
        #pragma unroll
        for (int t = 0; t < 3; t++) {
            float mx = fmaxf(s[t][0], fmaxf(s[t][1], s[t][2]));
            float e0 = expf(s[t][0] - mx);
            float e1 = expf(s[t][1] - mx);
            float e2 = expf(s[t][2] - mx);
            float inv = 1.f / (e0 + e1 + e2);
            u32 cw[4];
            #pragma unroll
            for (int j = 0; j < 8; j += 2) {
                float c0 = (e0 * v[0][j]   + e1 * v[1][j]   + e2 * v[2][j])   * inv;
                float c1 = (e0 * v[0][j+1] + e1 * v[1][j+1] + e2 * v[2][j+1]) * inv;
                cw[j >> 1] = bf2bits(__floats2bfloat162_rn(c0, c1));
            }
            int row = tb * 3 + t;
            u32 off = (u32)(row * 128 + ctx_inb);
            off ^= (off >> 3) & 0x70;
            asm volatile("st.shared.v4.b32 [%0], {%1,%2,%3,%4};"
                         :: "r"(base + ctx_ch * 12288 + off),
                            "r"(cw[0]), "r"(cw[1]), "r"(cw[2]), "r"(cw[3]));
        }
    }
    __syncthreads();

    // ---------------- phase 3: out-proj (ctx x out_w hi) -> g_att bf16 -----
    #pragma unroll 1
    for (int nt2 = 0; nt2 < 2; nt2++) {
        float acc[3][4][4];
        #pragma unroll
        for (int i = 0; i < 3; i++)
            #pragma unroll
            for (int j = 0; j < 4; j++)
                #pragma unroll
                for (int q = 0; q < 4; q++) acc[i][j][q] = 0.f;

        #pragma unroll
        for (int kc = 0; kc < 4; kc++) {
            const int gc = nt2 * 4 + kc;
            asm volatile("cp.async.wait_group 0;");
            __syncthreads();
            if (gc + 1 < 8) {
                load_tile<128, 1024>(wbase + ((gc + 1) & 1) * 16384,
                                     Wo + (size_t)((gc + 1) >> 2) * 131072 + ((gc + 1) & 3) * 128);
                asm volatile("cp.async.commit_group;");
            }

            const u32 As = base + kc * 12288;
            const u32 Bs = wbase + (gc & 1) * 16384;
            #pragma unroll
            for (int ks = 0; ks < 4; ks++) {
                u32 a[3][4];
                #pragma unroll
                for (int fm = 0; fm < 3; fm++) {
                    int row = warp_m * 48 + fm * 16 + a_row_base;
                    u32 kb = (u32)(ks * 32 + a_kb_sel);
                    u32 ad = As + row * 128 + (kb ^ ((row & 7) << 4));
                    ldsm4(ad, a[fm][0], a[fm][1], a[fm][2], a[fm][3]);
                }
                u32 b[2][4];
                #pragma unroll
                for (int fn = 0; fn < 2; fn++) {
                    int row = warp_n * 32 + fn * 16 + b_row_base;
                    u32 kb = (u32)(ks * 32 + b_kb_sel);
                    u32 bd = Bs + row * 128 + (kb ^ ((row & 7) << 4));
                    ldsm4(bd, b[fn][0], b[fn][1], b[fn][2], b[fn][3]);
                }
                #pragma unroll
                for (int fm = 0; fm < 3; fm++)
                    #pragma unroll
                    for (int f8 = 0; f8 < 4; f8++)
                        mma16816(acc[fm][f8], a[fm],
                                 b[f8 >> 1][(f8 & 1) * 2], b[f8 >> 1][(f8 & 1) * 2 + 1]);
            }
        }

        #pragma unroll
        for (int fm = 0; fm < 3; fm++) {
            const int r = warp_m * 48 + fm * 16 + quad;
            #pragma unroll
            for (int f8 = 0; f8 < 4; f8++) {
                const int ncol = nt2 * 128 + warp_n * 32 + f8 * 8 + 2 * tq;
                float2 bv = *(const float2*)&ob[ncol];
                u32 lo = bf2bits(__floats2bfloat162_rn(acc[fm][f8][0] + bv.x,
                                                       acc[fm][f8][1] + bv.y));
                u32 hi = bf2bits(__floats2bfloat162_rn(acc[fm][f8][2] + bv.x,
                                                       acc[fm][f8][3] + bv.y));
                *(u32*)&g_att[(size_t)(m0 + r) * 256 + ncol]     = lo;
                *(u32*)&g_att[(size_t)(m0 + r + 8) * 256 + ncol] = hi;
            }
        }
    }
}

// ---------------------------------------------------------------------------
// fuse: x = att(bf16) + feat; LN1, gate softmax, fused (fp32), LN2 -> g_hh.
// ---------------------------------------------------------------------------
__global__ __launch_bounds__(256)
void fuse_k(const float* __restrict__ s0, const float* __restrict__ s1,
            const float* __restrict__ s2,
            const float* __restrict__ ln1g, const float* __restrict__ ln1b,
            const float* __restrict__ gw,   const float* __restrict__ gb,
            const float* __restrict__ ln2g, const float* __restrict__ ln2b,
            float* __restrict__ out_fused, int B)
{
    __shared__ float s_gw[2304];
    __shared__ float s_ln[1024];
    for (int i = threadIdx.x; i < 2304; i += 256) s_gw[i] = gw[i];
    if (threadIdx.x < 256) {
        int i = threadIdx.x;
        s_ln[i]       = ln1g[i];
        s_ln[256 + i] = ln1b[i];
        s_ln[512 + i] = ln2g[i];
        s_ln[768 + i] = ln2b[i];
    }
    __syncthreads();

    int warp = threadIdx.x >> 5, lane = threadIdx.x & 31;
    int d0 = lane * 8;
    const float* srcs[3] = {s0, s1, s2};

    for (int b = blockIdx.x * 8 + warp; b < B; b += gridDim.x * 8) {
        float y[3][8];
        float gpart[3] = {0.f, 0.f, 0.f};
        #pragma unroll
        for (int t = 0; t < 3; t++) {
            float iv[8];
            const float* in = srcs[t] + (size_t)b * 256;
            *(float4*)&iv[0] = *(const float4*)(in + d0);
            *(float4*)&iv[4] = *(const float4*)(in + d0 + 4);
            float x[8];
            uint4 ar = *(const uint4*)(g_att + ((size_t)b * 3 + t) * 256 + d0);
            const u32* aw = (const u32*)&ar;
            #pragma unroll
            for (int j = 0; j < 4; j++) {
                float2 af = __bfloat1622float2(*(const __nv_bfloat162*)&aw[j]);
                x[2*j]   = af.x + iv[2*j];
                x[2*j+1] = af.y + iv[2*j+1];
            }
            float s = 0.f;
            #pragma unroll
            for (int j = 0; j < 8; j++) s += x[j];
            s = wsum(s);
            float mu = s * (1.f / 256.f);
            float vv = 0.f;
            #pragma unroll
            for (int j = 0; j < 8; j++) { float d = x[j] - mu; vv += d * d; }
            vv = wsum(vv);
            float rs = rsqrtf(vv * (1.f / 256.f) + 1e-5f);
            #pragma unroll
            for (int j = 0; j < 8; j++)
                y[t][j] = (x[j] - mu) * rs * s_ln[d0 + j] + s_ln[256 + d0 + j];

            #pragma unroll
            for (int g = 0; g < 3; g++) {
                const float* wrow = s_gw + g * 768 + t * 256 + d0;
                #pragma unroll
                for (int j = 0; j < 8; j++) gpart[g] += iv[j] * wrow[j];
            }
        }
        float gl[3];
        #pragma unroll
        for (int g = 0; g < 3; g++) gl[g] = wsum(gpart[g]) + gb[g];
        float mx = fmaxf(gl[0], fmaxf(gl[1], gl[2]));
        float e0 = expf(gl[0] - mx), e1 = expf(gl[1] - mx), e2 = expf(gl[2] - mx);
        float inv = 1.f / (e0 + e1 + e2);
        float w0 = e0 * inv, w1 = e1 * inv, w2 = e2 * inv;

        float f[8];
        #pragma unroll
        for (int j = 0; j < 8; j++)
            f[j] = w0 * y[0][j] + w1 * y[1][j] + w2 * y[2][j];
        if (out_fused) {
            float* orow = out_fused + (size_t)b * 256 + d0;
            *(float4*)orow       = *(float4*)&f[0];
            *(float4*)(orow + 4) = *(float4*)&f[4];
        }
        float s2v = 0.f;
        #pragma unroll
        for (int j = 0; j < 8; j++) s2v += f[j];
        s2v = wsum(s2v);
        float mu2 = s2v * (1.f / 256.f);
        float vv2 = 0.f;
        #pragma unroll
        for (int j = 0; j < 8; j++) { float d = f[j] - mu2; vv2 += d * d; }
        vv2 = wsum(vv2);
        float rs2 = rsqrtf(vv2 * (1.f / 256.f) + 1e-5f);
        u32 hi[4], lo[4];
        #pragma unroll
        for (int j = 0; j < 8; j += 2) {
            float h0 = (f[j]   - mu2) * rs2 * s_ln[512 + d0 + j]   + s_ln[768 + d0 + j];
            float h1 = (f[j+1] - mu2) * rs2 * s_ln[512 + d0 + j+1] + s_ln[768 + d0 + j+1];
            split2(h0, h1, hi[j >> 1], lo[j >> 1]);
        }
        __nv_bfloat16* hrow = g_hh + (size_t)b * 512 + d0;
        *(uint4*)hrow         = *(uint4*)hi;
        *(uint4*)(hrow + 256) = *(uint4*)lo;
    }
}

// ---------------------------------------------------------------------------
// deephead (occ-2): M_TILE=64, single-sync pipeline (wait then sync),
// arithmetic chunk indices. smem: A 2x8K | W 2x16K | H2 8x8K = 112K.
// ---------------------------------------------------------------------------
__device__ __forceinline__ int a_idx12f(int kc) { return (kc < 8) ? (kc & 3) : (kc - 4); }
__device__ __forceinline__ int w_idx12f(int kc) { return (kc < 8) ? kc : (kc - 8); }

__global__ __launch_bounds__(256, 2)
void deephead(const float* __restrict__ b1, const float* __restrict__ b2,
              const float* __restrict__ w3p, const float* __restrict__ b3p,
              float* __restrict__ outp)
{
    extern __shared__ char dsm[];
    char* dbase = (char*)((((uintptr_t)dsm) + 127) & ~(uintptr_t)127);
    u32 base = smem_u32(dbase);
    const u32 abase = base;              // 2 x 8192
    const u32 wbase = base + 16384;      // 2 x 16384
    const u32 hbase = base + 49152;      // 8 x 8192

    const int tid = threadIdx.x;
    const int lane = tid & 31;
    const int wid = tid >> 5;
    const int warp_m = wid & 1;
    const int warp_n = wid >> 1;
    const int m0 = blockIdx.x * 64;

    const char* Ab  = (const char*)g_hh + (size_t)m0 * 1024;
    const char* W1b = (const char*)(g_w + WOFF_W1);
    const char* W2b = (const char*)(g_w + WOFF_W2);

    const int a_mi = lane >> 3;
    const int a_row_base = ((a_mi & 1) << 3) + (lane & 7);
    const int a_kb_sel = (lane >> 4) << 4;
    const int b_row_base = ((a_mi >> 1) << 3) + (lane & 7);
    const int b_kb_sel = ((lane >> 3) & 1) << 4;
    const int quad = lane >> 2, tq = lane & 3;

    float acc[2][4][4];
    #pragma unroll
    for (int i = 0; i < 2; i++)
        #pragma unroll
        for (int j = 0; j < 4; j++)
            #pragma unroll
            for (int q = 0; q < 4; q++) acc[i][j][q] = 0.f;

    load_tile<64, 1024>(abase, Ab);
    load_tile<128, 1024>(wbase, W1b);
    asm volatile("cp.async.commit_group;");

    // ---------------- phase 1: h2 = GELU(hh @ w1^T + b1) --------------------
    #pragma unroll 1
    for (int g = 0; g < 24; g++) {
        const int nt = g / 12, kc = g - nt * 12;
        asm volatile("cp.async.wait_group 0;");
        __syncthreads();
        if (g < 23) {
            const int g1 = g + 1;
            const int nt1 = g1 / 12, kc1 = g1 - nt1 * 12;
            load_tile<64, 1024>(abase + (g1 & 1) * 8192, Ab + a_idx12f(kc1) * 128);
            load_tile<128, 1024>(wbase + (g1 & 1) * 16384,
                                 W1b + (size_t)nt1 * 131072 + w_idx12f(kc1) * 128);
            asm volatile("cp.async.commit_group;");
        } else {
            load_tile<128, 1024>(wbase, W2b);
            asm volatile("cp.async.commit_group;");
        }

        const u32 As = abase + (g & 1) * 8192;
        const u32 Bs = wbase + (g & 1) * 16384;
        #pragma unroll
        for (int ks = 0; ks < 4; ks++) {
            u32 a[2][4];
            #pragma unroll
            for (int fm = 0; fm < 2; fm++) {
                int row = warp_m * 32 + fm * 16 + a_row_base;
                u32 kb = (u32)(ks * 32 + a_kb_sel);
                u32 ad = As + row * 128 + (kb ^ ((row & 7) << 4));
                ldsm4(ad, a[fm][0], a[fm][1], a[fm][2], a[fm][3]);
            }
            u32 b[2][4];
            #pragma unroll
            for (int fn = 0; fn < 2; fn++) {
                int row = warp_n * 32 + fn * 16 + b_row_base;
                u32 kb = (u32)(ks * 32 + b_kb_sel);
                u32 bd = Bs + row * 128 + (kb ^ ((row & 7) << 4));
                ldsm4(bd, b[fn][0], b[fn][1], b[fn][2], b[fn][3]);
            }
            #pragma unroll
            for (int fm = 0; fm < 2; fm++)
                #pragma unroll
                for (int f8 = 0; f8 < 4; f8++)
                    mma16816(acc[fm][f8], a[fm],
                             b[f8 >> 1][(f8 & 1) * 2], b[f8 >> 1][(f8 & 1) * 2 + 1]);
        }

        if (kc == 11) {
            // H2 slots written here are first read in phase 2 (after syncs).
            #pragma unroll
            for (int fm = 0; fm < 2; fm++) {
                #pragma unroll
                for (int f8 = 0; f8 < 4; f8++) {
                    const int ncol = nt * 128 + warp_n * 32 + f8 * 8 + 2 * tq;
                    float2 bv = *(const float2*)&b1[ncol];
                    float v0 = geluf(acc[fm][f8][0] + bv.x);
                    float v1 = geluf(acc[fm][f8][1] + bv.y);
                    float v2 = geluf(acc[fm][f8][2] + bv.x);
                    float v3 = geluf(acc[fm][f8][3] + bv.y);
                    u32 h0, l0, h1, l1;
                    split2(v0, v1, h0, l0);
                    split2(v2, v3, h1, l1);
                    const int chl = ncol >> 6;
                    const u32 hi_slot = hbase + chl * 8192;
                    const u32 lo_slot = hbase + 32768 + chl * 8192;
                    const int bb = (ncol & 63) * 2;
                    const int r0 = warp_m * 32 + fm * 16 + quad;
                    #pragma unroll
                    for (int wh = 0; wh < 2; wh++) {
                        int row = r0 + wh * 8;
                        u32 off = (u32)(row * 128 + (bb & ~15));
                        off ^= (off >> 3) & 0x70;
                        off += (u32)(bb & 15);
                        u32 hv = wh ? h1 : h0;
                        u32 lv = wh ? l1 : l0;
                        asm volatile("st.shared.b32 [%0], %1;" :: "r"(hi_slot + off), "r"(hv));
                        asm volatile("st.shared.b32 [%0], %1;" :: "r"(lo_slot + off), "r"(lv));
                    }
                    acc[fm][f8][0] = 0.f; acc[fm][f8][1] = 0.f;
                    acc[fm][f8][2] = 0.f; acc[fm][f8][3] = 0.f;
                }
            }
        }
    }

    // ---------------- phase 2: h3 = GELU(h2 @ w2^T + b2) --------------------
    #pragma unroll 1
    for (int j = 0; j < 12; j++) {
        asm volatile("cp.async.wait_group 0;");
        __syncthreads();
        if (j < 11) {
            load_tile<128, 1024>(wbase + ((25 + j) & 1) * 16384,
                                 W2b + w_idx12f(j + 1) * 128);
            asm volatile("cp.async.commit_group;");
        }

        const u32 As = hbase + a_idx12f(j) * 8192;
        const u32 Bs = wbase + ((24 + j) & 1) * 16384;
        #pragma unroll
        for (int ks = 0; ks < 4; ks++) {
            u32 a[2][4];
            #pragma unroll
            for (int fm = 0; fm < 2; fm++) {
                int row = warp_m * 32 + fm * 16 + a_row_base;
                u32 kb = (u32)(ks * 32 + a_kb_sel);
                u32 ad = As + row * 128 + (kb ^ ((row & 7) << 4));
                ldsm4(ad, a[fm][0], a[fm][1], a[fm][2], a[fm][3]);
            }
            u32 b[2][4];
            #pragma unroll
            for (int fn = 0; fn < 2; fn++) {
                int row = warp_n * 32 + fn * 16 + b_row_base;
                u32 kb = (u32)(ks * 32 + b_kb_sel);
                u32 bd = Bs + row * 128 + (kb ^ ((row & 7) << 4));
                ldsm4(bd, b[fn][0], b[fn][1], b[fn][2], b[fn][3]);
            }
            #pragma unroll
            for (int fm = 0; fm < 2; fm++)
                #pragma unroll
                for (int f8 = 0; f8 < 4; f8++)
                    mma16816(acc[fm][f8], a[fm],
                             b[f8 >> 1][(f8 & 1) * 2], b[f8 >> 1][(f8 & 1) * 2 + 1]);
        }
    }
    __syncthreads();   // all MMA reads of H2 done before overwriting with h3

    float* h3_s = (float*)(dbase + 49152);
    #pragma unroll
    for (int fm = 0; fm < 2; fm++) {
        #pragma unroll
        for (int f8 = 0; f8 < 4; f8++) {
            const int n = warp_n * 32 + f8 * 8 + 2 * tq;
            float2 bv = *(const float2*)&b2[n];
            int rl = warp_m * 32 + fm * 16 + quad;
            *(float2*)&h3_s[rl * 128 + n] =
                {geluf(acc[fm][f8][0] + bv.x), geluf(acc[fm][f8][1] + bv.y)};
            *(float2*)&h3_s[(rl + 8) * 128 + n] =
                {geluf(acc[fm][f8][2] + bv.x), geluf(acc[fm][f8][3] + bv.y)};
        }
    }
    __syncthreads();

    const int d0 = lane * 4;
    float4 wv[7];
    #pragma unroll
    for (int j = 0; j < 7; j++) wv[j] = *(const float4*)&w3p[j * 128 + d0];
    #pragma unroll 1
    for (int rr = 0; rr < 8; rr++) {
        int row = wid * 8 + rr;
        float4 h = *(const float4*)&h3_s[row * 128 + d0];
        float r[7];
        #pragma unroll
        for (int j = 0; j < 7; j++) {
            float p = h.x * wv[j].x + h.y * wv[j].y + h.z * wv[j].z + h.w * wv[j].w;
            r[j] = wsum(p);
        }
        if (lane == 0) {
            #pragma unroll
            for (int j = 0; j < 7; j++)
                outp[(size_t)(m0 + row) * 7 + j] = r[j] + b3p[j];
        }
    }
}

// ---------------------------------------------------------------------------
extern "C" void kernel_launch(void* const* d_in, const int* in_sizes, int n_in,
                              void* d_out, int out_size)
{
    const float* f_swin    = (const float*)d_in[0];
    const float* f_maxvit  = (const float*)d_in[1];
    const float* f_focal   = (const float*)d_in[2];
    const float* in_proj_w = (const float*)d_in[3];
    const float* in_proj_b = (const float*)d_in[4];
    const float* out_w  = (const float*)d_in[5];
    const float* out_b  = (const float*)d_in[6];
    const float* ln1_g  = (const float*)d_in[7];
    const float* ln1_b  = (const float*)d_in[8];
    const float* gate_w = (const float*)d_in[9];
    const float* gate_b = (const float*)d_in[10];
    const float* ln2_g  = (const float*)d_in[11];
    const float* ln2_b  = (const float*)d_in[12];
    const float* w1 = (const float*)d_in[13];
    const float* b1 = (const float*)d_in[14];
    const float* w2 = (const float*)d_in[15];
    const float* b2 = (const float*)d_in[16];
    const float* w3 = (const float*)d_in[17];
    const float* b3 = (const float*)d_in[18];

    int B = in_sizes[0] / 256;
    if (B > BMAX) B = BMAX;
    int rows3 = 3 * B;

    float* outp = (float*)d_out;
    float* out_logits = outp;
    float* out_fused = (out_size >= B * 263) ? (outp + (size_t)B * 7) : nullptr;

    const int SMEM_QA = 81920 + 96 * QKV_STRIDE + 1024;   // 231936 <= 232448
    const int SMEM_DH = 16384 + 32768 + 65536 + 128;      // 114816 (occ 2)
    cudaFuncSetAttribute(qkv_attn_out, cudaFuncAttributeMaxDynamicSharedMemorySize, SMEM_QA);
    cudaFuncSetAttribute(deephead, cudaFuncAttributeMaxDynamicSharedMemorySize, SMEM_DH);

    dim3 blk(256);

    conv_w_all<<<352, blk>>>(in_proj_w, out_w, w1, w2);
    // fused qkv + attention + out-proj (M_TILE=96, occ 1, single-sync pipeline)
    qkv_attn_out<<<rows3 / 96, blk, SMEM_QA>>>(in_proj_b, out_b,
                                               f_swin, f_maxvit, f_focal);
    // residual + LN1 + gate + fused + LN2
    fuse_k<<<2048, blk>>>(f_swin, f_maxvit, f_focal,
                          ln1_g, ln1_b, gate_w, gate_b, ln2_g, ln2_b,
                          out_fused, B);
    // deep head fused (occ 2, single-sync pipeline)
    deephead<<<B / 64, blk, SMEM_DH>>>(b1, b2, w3, b3, out_logits);
}

// round 17
// speedup vs baseline: 1.3778x; 1.0008x over previous
#include <cuda_runtime.h>
#include <cuda_bf16.h>
#include <math.h>
#include <stdint.h>

typedef unsigned int u32;
typedef unsigned long long u64;

#define BMAX 65536
#define QKV_STRIDE 1552   // 16B-aligned; 388 words % 32 = 4 -> quads on 8 banks

// ---------------------------------------------------------------------------
// Device scratch.
//  g_att : attention out (pre-residual) bf16 [3B, 256]
//  g_hh  : LN2(fused) split bf16             [B, 512]  (hi | lo)
//  g_w   : split weights                     [rows, 512]
// ---------------------------------------------------------------------------
__device__ __nv_bfloat16 g_att[(size_t)BMAX * 3 * 256];
__device__ __nv_bfloat16 g_hh [(size_t)BMAX * 512];
__device__ __nv_bfloat16 g_w  [(size_t)(768 + 256 + 256 + 128) * 512];

#define WOFF_QKV 0
#define WOFF_OUT (768 * 512)
#define WOFF_W1  ((768 + 256) * 512)
#define WOFF_W2  ((768 + 512) * 512)

__device__ __forceinline__ u32 smem_u32(const void* p) {
    u32 a;
    asm("{ .reg .u64 t; cvta.to.shared.u64 t, %1; cvt.u32.u64 %0, t; }" : "=r"(a) : "l"(p));
    return a;
}
__device__ __forceinline__ float geluf(float x) {
    return 0.5f * x * (1.0f + erff(x * 0.7071067811865476f));
}
__device__ __forceinline__ float wsum(float v) {
    #pragma unroll
    for (int o = 16; o > 0; o >>= 1) v += __shfl_xor_sync(0xffffffffu, v, o);
    return v;
}
__device__ __forceinline__ u32 bf2bits(__nv_bfloat162 h) {
    return *reinterpret_cast<u32*>(&h);
}
__device__ __forceinline__ void split2(float a, float b, u32& h, u32& l) {
    __nv_bfloat162 hh = __floats2bfloat162_rn(a, b);
    float ra = a - __bfloat162float(hh.x);
    float rb = b - __bfloat162float(hh.y);
    __nv_bfloat162 ll = __floats2bfloat162_rn(ra, rb);
    h = bf2bits(hh);
    l = bf2bits(ll);
}

// ---------------------------------------------------------------------------
// merged weight conversion: fp32 [rows,256] -> split bf16 [rows,512]
// ---------------------------------------------------------------------------
__global__ __launch_bounds__(256)
void conv_w_all(const float* __restrict__ ipw, const float* __restrict__ ow,
                const float* __restrict__ w1, const float* __restrict__ w2)
{
    int id = blockIdx.x * 256 + threadIdx.x;
    int row = id >> 6;
    int k = (id & 63) << 2;
    const float* src; int r, woff;
    if (row < 768)       { src = ipw; r = row;        woff = WOFF_QKV; }
    else if (row < 1024) { src = ow;  r = row - 768;  woff = WOFF_OUT; }
    else if (row < 1280) { src = w1;  r = row - 1024; woff = WOFF_W1; }
    else                 { src = w2;  r = row - 1280; woff = WOFF_W2; }
    float4 v = *(const float4*)(src + (size_t)r * 256 + k);
    u32 h0, l0, h1, l1;
    split2(v.x, v.y, h0, l0);
    split2(v.z, v.w, h1, l1);
    __nv_bfloat16* dst = g_w + (size_t)woff + (size_t)r * 512;
    u32* hp = (u32*)(dst + k);
    u32* lp = (u32*)(dst + 256 + k);
    hp[0] = h0; hp[1] = h1;
    lp[0] = l0; lp[1] = l1;
}

// ---------------------------------------------------------------------------
// MMA helpers
// ---------------------------------------------------------------------------
__device__ __forceinline__ void ldsm4(u32 addr, u32& r0, u32& r1, u32& r2, u32& r3) {
    asm volatile("ldmatrix.sync.aligned.m8n8.x4.shared.b16 {%0,%1,%2,%3}, [%4];"
                 : "=r"(r0), "=r"(r1), "=r"(r2), "=r"(r3) : "r"(addr));
}
__device__ __forceinline__ void mma16816(float* c, const u32* a, u32 b0, u32 b1) {
    asm volatile(
        "mma.sync.aligned.m16n8k16.row.col.f32.bf16.bf16.f32 "
        "{%0,%1,%2,%3}, {%4,%5,%6,%7}, {%8,%9}, {%0,%1,%2,%3};"
        : "+f"(c[0]), "+f"(c[1]), "+f"(c[2]), "+f"(c[3])
        : "r"(a[0]), "r"(a[1]), "r"(a[2]), "r"(a[3]), "r"(b0), "r"(b1));
}

// load NROWS x 128B chunk into SW128-swizzled smem via cp.async
template<int NROWS, int ROWB>
__device__ __forceinline__ void load_tile(u32 sbase, const char* gb) {
    constexpr int ITERS = NROWS * 8 / 256;
    int tid = threadIdx.x;
    #pragma unroll
    for (int i = 0; i < ITERS; i++) {
        int seg = i * 256 + tid;
        int r = seg >> 3, c = seg & 7;
        u32 off = (u32)(r * 128 + c * 16);
        off ^= (off >> 3) & 0x70;
        asm volatile("cp.async.cg.shared.global [%0], [%1], 16;"
                     :: "r"(sbase + off), "l"(gb + (size_t)r * ROWB + c * 16));
    }
}

// 96-row feature chunk: fp32 -> bf16 direct into swizzled smem
__device__ __forceinline__ void load_Afeat96(u32 sbase, int m0, int c,
                                             const float* __restrict__ s0,
                                             const float* __restrict__ s1,
                                             const float* __restrict__ s2)
{
    int tid = threadIdx.x;
    #pragma unroll
    for (int i = 0; i < 3; i++) {
        int seg = i * 256 + tid;
        int r = seg >> 3, c8 = seg & 7;
        int m = m0 + r;
        int b = m / 3, t = m - 3 * b;
        const float* src = ((t == 0) ? s0 : (t == 1) ? s1 : s2)
                           + (size_t)b * 256 + c * 64 + c8 * 8;
        float4 v0 = *(const float4*)src;
        float4 v1 = *(const float4*)(src + 4);
        u32 w0 = bf2bits(__floats2bfloat162_rn(v0.x, v0.y));
        u32 w1 = bf2bits(__floats2bfloat162_rn(v0.z, v0.w));
        u32 w2 = bf2bits(__floats2bfloat162_rn(v1.x, v1.y));
        u32 w3 = bf2bits(__floats2bfloat162_rn(v1.z, v1.w));
        u32 off = (u32)(r * 128 + c8 * 16);
        off ^= (off >> 3) & 0x70;
        asm volatile("st.shared.v4.b32 [%0], {%1,%2,%3,%4};"
                     :: "r"(sbase + off), "r"(w0), "r"(w1), "r"(w2), "r"(w3));
    }
}

// ---------------------------------------------------------------------------
// qkv_attn_out: fused qkv projection + attention + out-proj.
//  M_TILE = 96 rows = 32 whole batches. Single-sync double-buffered pipeline:
//  per chunk: wait_group 0; sync; issue load(g+1); MMA(g).   (R13-verified)
// smem: A 4x12288 (48K) | W 2x16384 (32K) | qkv 96x1552 (145.5K) ~ 226.5K
// ---------------------------------------------------------------------------
__global__ __launch_bounds__(256)
void qkv_attn_out(const float* __restrict__ ipb, const float* __restrict__ ob,
                  const float* __restrict__ s0, const float* __restrict__ s1,
                  const float* __restrict__ s2)
{
    extern __shared__ char dsm[];
    char* dbase = (char*)((((uintptr_t)dsm) + 1023) & ~(uintptr_t)1023);
    u32 base = smem_u32(dbase);
    const u32 wbase = base + 49152;
    char* qkv_s = dbase + 81920;              // [96][768] bf16, row stride 1552B

    const int tid = threadIdx.x;
    const int lane = tid & 31;
    const int wid = tid >> 5;
    const int warp_m = wid & 1;               // 0..1 -> 48 rows
    const int warp_n = wid >> 1;              // 0..3 -> 32 cols
    const int m0 = blockIdx.x * 96;

    const char* Wq = (const char*)(g_w + WOFF_QKV);
    const char* Wo = (const char*)(g_w + WOFF_OUT);

    const int a_mi = lane >> 3;
    const int a_row_base = ((a_mi & 1) << 3) + (lane & 7);
    const int a_kb_sel = (lane >> 4) << 4;
    const int b_row_base = ((a_mi >> 1) << 3) + (lane & 7);
    const int b_kb_sel = ((lane >> 3) & 1) << 4;
    const int quad = lane >> 2, tq = lane & 3;

    // ---------------- phase 1: qkv GEMM ----------------
    load_tile<128, 1024>(wbase, Wq);          // chunk 0
    asm volatile("cp.async.commit_group;");
    #pragma unroll
    for (int c = 0; c < 4; c++)
        load_Afeat96(base + c * 12288, m0, c, s0, s1, s2);

    #pragma unroll 1
    for (int nt = 0; nt < 6; nt++) {
        float acc[3][4][4];
        #pragma unroll
        for (int i = 0; i < 3; i++)
            #pragma unroll
            for (int j = 0; j < 4; j++)
                #pragma unroll
                for (int q = 0; q < 4; q++) acc[i][j][q] = 0.f;

        #pragma unroll
        for (int kc = 0; kc < 4; kc++) {
            const int gc = nt * 4 + kc;
            asm volatile("cp.async.wait_group 0;");
            __syncthreads();
            if (gc + 1 < 24) {
                const int nnt = (gc + 1) >> 2, nkc = (gc + 1) & 3;
                load_tile<128, 1024>(wbase + ((gc + 1) & 1) * 16384,
                                     Wq + (size_t)nnt * 131072 + nkc * 128);
                asm volatile("cp.async.commit_group;");
            } else {
                // prefetch out-proj W chunk 0 (into buffer (24&1)=0)
                load_tile<128, 1024>(wbase, Wo);
                asm volatile("cp.async.commit_group;");
            }

            const u32 As = base + kc * 12288;
            const u32 Bs = wbase + (gc & 1) * 16384;
            #pragma unroll
            for (int ks = 0; ks < 4; ks++) {
                u32 a[3][4];
                #pragma unroll
                for (int fm = 0; fm < 3; fm++) {
                    int row = warp_m * 48 + fm * 16 + a_row_base;
                    u32 kb = (u32)(ks * 32 + a_kb_sel);
                    u32 ad = As + row * 128 + (kb ^ ((row & 7) << 4));
                    ldsm4(ad, a[fm][0], a[fm][1], a[fm][2], a[fm][3]);
                }
                u32 b[2][4];
                #pragma unroll
                for (int fn = 0; fn < 2; fn++) {
                    int row = warp_n * 32 + fn * 16 + b_row_base;
                    u32 kb = (u32)(ks * 32 + b_kb_sel);
                    u32 bd = Bs + row * 128 + (kb ^ ((row & 7) << 4));
                    ldsm4(bd, b[fn][0], b[fn][1], b[fn][2], b[fn][3]);
                }
                #pragma unroll
                for (int fm = 0; fm < 3; fm++)
                    #pragma unroll
                    for (int f8 = 0; f8 < 4; f8++)
                        mma16816(acc[fm][f8], a[fm],
                                 b[f8 >> 1][(f8 & 1) * 2], b[f8 >> 1][(f8 & 1) * 2 + 1]);
            }
        }

        // park this n-tile's qkv in smem (+bias, bf16); qkv_s not read until
        // the sync after phase 1, so no barrier needed here.
        #pragma unroll
        for (int fm = 0; fm < 3; fm++) {
            const int r = warp_m * 48 + fm * 16 + quad;
            #pragma unroll
            for (int f8 = 0; f8 < 4; f8++) {
                const int ncol = nt * 128 + warp_n * 32 + f8 * 8 + 2 * tq;
                float2 bv = *(const float2*)&ipb[ncol];
                u32 lo = bf2bits(__floats2bfloat162_rn(acc[fm][f8][0] + bv.x,
                                                       acc[fm][f8][1] + bv.y));
                u32 hi = bf2bits(__floats2bfloat162_rn(acc[fm][f8][2] + bv.x,
                                                       acc[fm][f8][3] + bv.y));
                *(u32*)(qkv_s + (size_t)r * QKV_STRIDE + ncol * 2)       = lo;
                *(u32*)(qkv_s + (size_t)(r + 8) * QKV_STRIDE + ncol * 2) = hi;
            }
        }
    }
    __syncthreads();      // qkv_s fully parked; Wo chunk 0 in flight

    // ---------------- phase 2: attention; ctx -> A region ----------------
    const int d0 = lane * 8;
    const int ctx_ch = lane >> 3;
    const int ctx_inb = (d0 & 63) * 2;
    #pragma unroll 1
    for (int bl = 0; bl < 4; bl++) {
        int tb = wid * 4 + bl;

        float q[3][8], k[3][8], v[3][8];
        #pragma unroll
        for (int t = 0; t < 3; t++) {
            const char* rp = qkv_s + (size_t)(tb * 3 + t) * QKV_STRIDE + d0 * 2;
            uint4 qr = *(const uint4*)rp;
            uint4 kr = *(const uint4*)(rp + 512);
            uint4 vr = *(const uint4*)(rp + 1024);
            const u32* qw = (const u32*)&qr;
            const u32* kw = (const u32*)&kr;
            const u32* vw = (const u32*)&vr;
            #pragma unroll
            for (int j = 0; j < 4; j++) {
                float2 qf = __bfloat1622float2(*(const __nv_bfloat162*)&qw[j]);
                float2 kf = __bfloat1622float2(*(const __nv_bfloat162*)&kw[j]);
                float2 vf = __bfloat1622float2(*(const __nv_bfloat162*)&vw[j]);
                q[t][2*j] = qf.x; q[t][2*j+1] = qf.y;
                k[t][2*j] = kf.x; k[t][2*j+1] = kf.y;
                v[t][2*j] = vf.x; v[t][2*j+1] = vf.y;
            }
        }
        float s[3][3];
        #pragma unroll
        for (int t = 0; t < 3; t++)
            #pragma unroll
            for (int u = 0; u < 3; u++) {
                float p = 0.f;
                #pragma unroll
                for (int j = 0; j < 8; j++) p += q[t][j] * k[u][j];
                p += __shfl_xor_sync(0xffffffffu, p, 1);
                p += __shfl_xor_sync(0xffffffffu, p, 2);
                p += __shfl_xor_sync(0xffffffffu, p, 4);
                s[t][u] = p * 0.125f;
            }
        #pragma unroll
        for (int t = 0; t < 3; t++) {
            float mx = fmaxf(s[t][0], fmaxf(s[t][1], s[t][2]));
            float e0 = expf(s[t][0] - mx);
            float e1 = expf(s[t][1] - mx);
            float e2 = expf(s[t][2] - mx);
            float inv = 1.f / (e0 + e1 + e2);
            u32 cw[4];
            #pragma unroll
            for (int j = 0; j < 8; j += 2) {
                float c0 = (e0 * v[0][j]   + e1 * v[1][j]   + e2 * v[2][j])   * inv;
                float c1 = (e0 * v[0][j+1] + e1 * v[1][j+1] + e2 * v[2][j+1]) * inv;
                cw[j >> 1] = bf2bits(__floats2bfloat162_rn(c0, c1));
            }
            int row = tb * 3 + t;
            u32 off = (u32)(row * 128 + ctx_inb);
            off ^= (off >> 3) & 0x70;
            asm volatile("st.shared.v4.b32 [%0], {%1,%2,%3,%4};"
                         :: "r"(base + ctx_ch * 12288 + off),
                            "r"(cw[0]), "r"(cw[1]), "r"(cw[2]), "r"(cw[3]));
        }
    }
    __syncthreads();

    // ---------------- phase 3: out-proj (ctx x out_w hi) -> g_att bf16 -----
    #pragma unroll 1
    for (int nt2 = 0; nt2 < 2; nt2++) {
        float acc[3][4][4];
        #pragma unroll
        for (int i = 0; i < 3; i++)
            #pragma unroll
            for (int j = 0; j < 4; j++)
                #pragma unroll
                for (int q = 0; q < 4; q++) acc[i][j][q] = 0.f;

        #pragma unroll
        for (int kc = 0; kc < 4; kc++) {
            const int gc = nt2 * 4 + kc;
            asm volatile("cp.async.wait_group 0;");
            __syncthreads();
            if (gc + 1 < 8) {
                load_tile<128, 1024>(wbase + ((gc + 1) & 1) * 16384,
                                     Wo + (size_t)((gc + 1) >> 2) * 131072 + ((gc + 1) & 3) * 128);
                asm volatile("cp.async.commit_group;");
            }

            const u32 As = base + kc * 12288;
            const u32 Bs = wbase + (gc & 1) * 16384;
            #pragma unroll
            for (int ks = 0; ks < 4; ks++) {
                u32 a[3][4];
                #pragma unroll
                for (int fm = 0; fm < 3; fm++) {
                    int row = warp_m * 48 + fm * 16 + a_row_base;
                    u32 kb = (u32)(ks * 32 + a_kb_sel);
                    u32 ad = As + row * 128 + (kb ^ ((row & 7) << 4));
                    ldsm4(ad, a[fm][0], a[fm][1], a[fm][2], a[fm][3]);
                }
                u32 b[2][4];
                #pragma unroll
                for (int fn = 0; fn < 2; fn++) {
                    int row = warp_n * 32 + fn * 16 + b_row_base;
                    u32 kb = (u32)(ks * 32 + b_kb_sel);
                    u32 bd = Bs + row * 128 + (kb ^ ((row & 7) << 4));
                    ldsm4(bd, b[fn][0], b[fn][1], b[fn][2], b[fn][3]);
                }
                #pragma unroll
                for (int fm = 0; fm < 3; fm++)
                    #pragma unroll
                    for (int f8 = 0; f8 < 4; f8++)
                        mma16816(acc[fm][f8], a[fm],
                                 b[f8 >> 1][(f8 & 1) * 2], b[f8 >> 1][(f8 & 1) * 2 + 1]);
            }
        }

        #pragma unroll
        for (int fm = 0; fm < 3; fm++) {
            const int r = warp_m * 48 + fm * 16 + quad;
            #pragma unroll
            for (int f8 = 0; f8 < 4; f8++) {
                const int ncol = nt2 * 128 + warp_n * 32 + f8 * 8 + 2 * tq;
                float2 bv = *(const float2*)&ob[ncol];
                u32 lo = bf2bits(__floats2bfloat162_rn(acc[fm][f8][0] + bv.x,
                                                       acc[fm][f8][1] + bv.y));
                u32 hi = bf2bits(__floats2bfloat162_rn(acc[fm][f8][2] + bv.x,
                                                       acc[fm][f8][3] + bv.y));
                *(u32*)&g_att[(size_t)(m0 + r) * 256 + ncol]     = lo;
                *(u32*)&g_att[(size_t)(m0 + r + 8) * 256 + ncol] = hi;
            }
        }
    }
}

// ---------------------------------------------------------------------------
// fuse: x = att(bf16) + feat; LN1, gate softmax, fused (fp32), LN2 -> g_hh.
// ---------------------------------------------------------------------------
__global__ __launch_bounds__(256)
void fuse_k(const float* __restrict__ s0, const float* __restrict__ s1,
            const float* __restrict__ s2,
            const float* __restrict__ ln1g, const float* __restrict__ ln1b,
            const float* __restrict__ gw,   const float* __restrict__ gb,
            const float* __restrict__ ln2g, const float* __restrict__ ln2b,
            float* __restrict__ out_fused, int B)
{
    __shared__ float s_gw[2304];
    __shared__ float s_ln[1024];
    for (int i = threadIdx.x; i < 2304; i += 256) s_gw[i] = gw[i];
    if (threadIdx.x < 256) {
        int i = threadIdx.x;
        s_ln[i]       = ln1g[i];
        s_ln[256 + i] = ln1b[i];
        s_ln[512 + i] = ln2g[i];
        s_ln[768 + i] = ln2b[i];
    }
    __syncthreads();

    int warp = threadIdx.x >> 5, lane = threadIdx.x & 31;
    int d0 = lane * 8;
    const float* srcs[3] = {s0, s1, s2};

    for (int b = blockIdx.x * 8 + warp; b < B; b += gridDim.x * 8) {
        float y[3][8];
        float gpart[3] = {0.f, 0.f, 0.f};
        #pragma unroll
        for (int t = 0; t < 3; t++) {
            float iv[8];
            const float* in = srcs[t] + (size_t)b * 256;
            *(float4*)&iv[0] = *(const float4*)(in + d0);
            *(float4*)&iv[4] = *(const float4*)(in + d0 + 4);
            float x[8];
            uint4 ar = *(const uint4*)(g_att + ((size_t)b * 3 + t) * 256 + d0);
            const u32* aw = (const u32*)&ar;
            #pragma unroll
            for (int j = 0; j < 4; j++) {
                float2 af = __bfloat1622float2(*(const __nv_bfloat162*)&aw[j]);
                x[2*j]   = af.x + iv[2*j];
                x[2*j+1] = af.y + iv[2*j+1];
            }
            float s = 0.f;
            #pragma unroll
            for (int j = 0; j < 8; j++) s += x[j];
            s = wsum(s);
            float mu = s * (1.f / 256.f);
            float vv = 0.f;
            #pragma unroll
            for (int j = 0; j < 8; j++) { float d = x[j] - mu; vv += d * d; }
            vv = wsum(vv);
            float rs = rsqrtf(vv * (1.f / 256.f) + 1e-5f);
            #pragma unroll
            for (int j = 0; j < 8; j++)
                y[t][j] = (x[j] - mu) * rs * s_ln[d0 + j] + s_ln[256 + d0 + j];

            #pragma unroll
            for (int g = 0; g < 3; g++) {
                const float* wrow = s_gw + g * 768 + t * 256 + d0;
                #pragma unroll
                for (int j = 0; j < 8; j++) gpart[g] += iv[j] * wrow[j];
            }
        }
        float gl[3];
        #pragma unroll
        for (int g = 0; g < 3; g++) gl[g] = wsum(gpart[g]) + gb[g];
        float mx = fmaxf(gl[0], fmaxf(gl[1], gl[2]));
        float e0 = expf(gl[0] - mx), e1 = expf(gl[1] - mx), e2 = expf(gl[2] - mx);
        float inv = 1.f / (e0 + e1 + e2);
        float w0 = e0 * inv, w1 = e1 * inv, w2 = e2 * inv;

        float f[8];
        #pragma unroll
        for (int j = 0; j < 8; j++)
            f[j] = w0 * y[0][j] + w1 * y[1][j] + w2 * y[2][j];
        if (out_fused) {
            float* orow = out_fused + (size_t)b * 256 + d0;
            *(float4*)orow       = *(float4*)&f[0];
            *(float4*)(orow + 4) = *(float4*)&f[4];
        }
        float s2v = 0.f;
        #pragma unroll
        for (int j = 0; j < 8; j++) s2v += f[j];
        s2v = wsum(s2v);
        float mu2 = s2v * (1.f / 256.f);
        float vv2 = 0.f;
        #pragma unroll
        for (int j = 0; j < 8; j++) { float d = f[j] - mu2; vv2 += d * d; }
        vv2 = wsum(vv2);
        float rs2 = rsqrtf(vv2 * (1.f / 256.f) + 1e-5f);
        u32 hi[4], lo[4];
        #pragma unroll
        for (int j = 0; j < 8; j += 2) {
            float h0 = (f[j]   - mu2) * rs2 * s_ln[512 + d0 + j]   + s_ln[768 + d0 + j];
            float h1 = (f[j+1] - mu2) * rs2 * s_ln[512 + d0 + j+1] + s_ln[768 + d0 + j+1];
            split2(h0, h1, hi[j >> 1], lo[j >> 1]);
        }
        __nv_bfloat16* hrow = g_hh + (size_t)b * 512 + d0;
        *(uint4*)hrow         = *(uint4*)hi;
        *(uint4*)(hrow + 256) = *(uint4*)lo;
    }
}

// ---------------------------------------------------------------------------
// deephead (occ-2): M_TILE=64, single-sync pipeline (wait then sync),
// arithmetic chunk indices. smem: A 2x8K | W 2x16K | H2 8x8K = 112K.
// ---------------------------------------------------------------------------
__device__ __forceinline__ int a_idx12f(int kc) { return (kc < 8) ? (kc & 3) : (kc - 4); }
__device__ __forceinline__ int w_idx12f(int kc) { return (kc < 8) ? kc : (kc - 8); }

__global__ __launch_bounds__(256, 2)
void deephead(const float* __restrict__ b1, const float* __restrict__ b2,
              const float* __restrict__ w3p, const float* __restrict__ b3p,
              float* __restrict__ outp)
{
    extern __shared__ char dsm[];
    char* dbase = (char*)((((uintptr_t)dsm) + 127) & ~(uintptr_t)127);
    u32 base = smem_u32(dbase);
    const u32 abase = base;              // 2 x 8192
    const u32 wbase = base + 16384;      // 2 x 16384
    const u32 hbase = base + 49152;      // 8 x 8192

    const int tid = threadIdx.x;
    const int lane = tid & 31;
    const int wid = tid >> 5;
    const int warp_m = wid & 1;
    const int warp_n = wid >> 1;
    const int m0 = blockIdx.x * 64;

    const char* Ab  = (const char*)g_hh + (size_t)m0 * 1024;
    const char* W1b = (const char*)(g_w + WOFF_W1);
    const char* W2b = (const char*)(g_w + WOFF_W2);

    const int a_mi = lane >> 3;
    const int a_row_base = ((a_mi & 1) << 3) + (lane & 7);
    const int a_kb_sel = (lane >> 4) << 4;
    const int b_row_base = ((a_mi >> 1) << 3) + (lane & 7);
    const int b_kb_sel = ((lane >> 3) & 1) << 4;
    const int quad = lane >> 2, tq = lane & 3;

    float acc[2][4][4];
    #pragma unroll
    for (int i = 0; i < 2; i++)
        #pragma unroll
        for (int j = 0; j < 4; j++)
            #pragma unroll
            for (int q = 0; q < 4; q++) acc[i][j][q] = 0.f;

    load_tile<64, 1024>(abase, Ab);
    load_tile<128, 1024>(wbase, W1b);
    asm volatile("cp.async.commit_group;");

    // ---------------- phase 1: h2 = GELU(hh @ w1^T + b1) --------------------
    #pragma unroll 1
    for (int g = 0; g < 24; g++) {
        const int nt = g / 12, kc = g - nt * 12;
        asm volatile("cp.async.wait_group 0;");
        __syncthreads();
        if (g < 23) {
            const int g1 = g + 1;
            const int nt1 = g1 / 12, kc1 = g1 - nt1 * 12;
            load_tile<64, 1024>(abase + (g1 & 1) * 8192, Ab + a_idx12f(kc1) * 128);
            load_tile<128, 1024>(wbase + (g1 & 1) * 16384,
                                 W1b + (size_t)nt1 * 131072 + w_idx12f(kc1) * 128);
            asm volatile("cp.async.commit_group;");
        } else {
            load_tile<128, 1024>(wbase, W2b);
            asm volatile("cp.async.commit_group;");
        }

        const u32 As = abase + (g & 1) * 8192;
        const u32 Bs = wbase + (g & 1) * 16384;
        #pragma unroll
        for (int ks = 0; ks < 4; ks++) {
            u32 a[2][4];
            #pragma unroll
            for (int fm = 0; fm < 2; fm++) {
                int row = warp_m * 32 + fm * 16 + a_row_base;
                u32 kb = (u32)(ks * 32 + a_kb_sel);
                u32 ad = As + row * 128 + (kb ^ ((row & 7) << 4));
                ldsm4(ad, a[fm][0], a[fm][1], a[fm][2], a[fm][3]);
            }
            u32 b[2][4];
            #pragma unroll
            for (int fn = 0; fn < 2; fn++) {
                int row = warp_n * 32 + fn * 16 + b_row_base;
                u32 kb = (u32)(ks * 32 + b_kb_sel);
                u32 bd = Bs + row * 128 + (kb ^ ((row & 7) << 4));
                ldsm4(bd, b[fn][0], b[fn][1], b[fn][2], b[fn][3]);
            }
            #pragma unroll
            for (int fm = 0; fm < 2; fm++)
                #pragma unroll
                for (int f8 = 0; f8 < 4; f8++)
                    mma16816(acc[fm][f8], a[fm],
                             b[f8 >> 1][(f8 & 1) * 2], b[f8 >> 1][(f8 & 1) * 2 + 1]);
        }

        if (kc == 11) {
            // H2 slots written here are first read in phase 2 (after syncs).
            #pragma unroll
            for (int fm = 0; fm < 2; fm++) {
                #pragma unroll
                for (int f8 = 0; f8 < 4; f8++) {
                    const int ncol = nt * 128 + warp_n * 32 + f8 * 8 + 2 * tq;
                    float2 bv = *(const float2*)&b1[ncol];
                    float v0 = geluf(acc[fm][f8][0] + bv.x);
                    float v1 = geluf(acc[fm][f8][1] + bv.y);
                    float v2 = geluf(acc[fm][f8][2] + bv.x);
                    float v3 = geluf(acc[fm][f8][3] + bv.y);
                    u32 h0, l0, h1, l1;
                    split2(v0, v1, h0, l0);
                    split2(v2, v3, h1, l1);
                    const int chl = ncol >> 6;
                    const u32 hi_slot = hbase + chl * 8192;
                    const u32 lo_slot = hbase + 32768 + chl * 8192;
                    const int bb = (ncol & 63) * 2;
                    const int r0 = warp_m * 32 + fm * 16 + quad;
                    #pragma unroll
                    for (int wh = 0; wh < 2; wh++) {
                        int row = r0 + wh * 8;
                        u32 off = (u32)(row * 128 + (bb & ~15));
                        off ^= (off >> 3) & 0x70;
                        off += (u32)(bb & 15);
                        u32 hv = wh ? h1 : h0;
                        u32 lv = wh ? l1 : l0;
                        asm volatile("st.shared.b32 [%0], %1;" :: "r"(hi_slot + off), "r"(hv));
                        asm volatile("st.shared.b32 [%0], %1;" :: "r"(lo_slot + off), "r"(lv));
                    }
                    acc[fm][f8][0] = 0.f; acc[fm][f8][1] = 0.f;
                    acc[fm][f8][2] = 0.f; acc[fm][f8][3] = 0.f;
                }
            }
        }
    }

    // ---------------- phase 2: h3 = GELU(h2 @ w2^T + b2) --------------------
    #pragma unroll 1
    for (int j = 0; j < 12; j++) {
        asm volatile("cp.async.wait_group 0;");
        __syncthreads();
        if (j < 11) {
            load_tile<128, 1024>(wbase + ((25 + j) & 1) * 16384,
                                 W2b + w_idx12f(j + 1) * 128);
            asm volatile("cp.async.commit_group;");
        }

        const u32 As = hbase + a_idx12f(j) * 8192;
        const u32 Bs = wbase + ((24 + j) & 1) * 16384;
        #pragma unroll
        for (int ks = 0; ks < 4; ks++) {
            u32 a[2][4];
            #pragma unroll
            for (int fm = 0; fm < 2; fm++) {
                int row = warp_m * 32 + fm * 16 + a_row_base;
                u32 kb = (u32)(ks * 32 + a_kb_sel);
                u32 ad = As + row * 128 + (kb ^ ((row & 7) << 4));
                ldsm4(ad, a[fm][0], a[fm][1], a[fm][2], a[fm][3]);
            }
            u32 b[2][4];
            #pragma unroll
            for (int fn = 0; fn < 2; fn++) {
                int row = warp_n * 32 + fn * 16 + b_row_base;
                u32 kb = (u32)(ks * 32 + b_kb_sel);
                u32 bd = Bs + row * 128 + (kb ^ ((row & 7) << 4));
                ldsm4(bd, b[fn][0], b[fn][1], b[fn][2], b[fn][3]);
            }
            #pragma unroll
            for (int fm = 0; fm < 2; fm++)
                #pragma unroll
                for (int f8 = 0; f8 < 4; f8++)
                    mma16816(acc[fm][f8], a[fm],
                             b[f8 >> 1][(f8 & 1) * 2], b[f8 >> 1][(f8 & 1) * 2 + 1]);
        }
    }
    __syncthreads();   // all MMA reads of H2 done before overwriting with h3

    float* h3_s = (float*)(dbase + 49152);
    #pragma unroll
    for (int fm = 0; fm < 2; fm++) {
        #pragma unroll
        for (int f8 = 0; f8 < 4; f8++) {
            const int n = warp_n * 32 + f8 * 8 + 2 * tq;
            float2 bv = *(const float2*)&b2[n];
            int rl = warp_m * 32 + fm * 16 + quad;
            *(float2*)&h3_s[rl * 128 + n] =
                {geluf(acc[fm][f8][0] + bv.x), geluf(acc[fm][f8][1] + bv.y)};
            *(float2*)&h3_s[(rl + 8) * 128 + n] =
                {geluf(acc[fm][f8][2] + bv.x), geluf(acc[fm][f8][3] + bv.y)};
        }
    }
    __syncthreads();

    const int d0 = lane * 4;
    float4 wv[7];
    #pragma unroll
    for (int j = 0; j < 7; j++) wv[j] = *(const float4*)&w3p[j * 128 + d0];
    #pragma unroll 1
    for (int rr = 0; rr < 8; rr++) {
        int row = wid * 8 + rr;
        float4 h = *(const float4*)&h3_s[row * 128 + d0];
        float r[7];
        #pragma unroll
        for (int j = 0; j < 7; j++) {
            float p = h.x * wv[j].x + h.y * wv[j].y + h.z * wv[j].z + h.w * wv[j].w;
            r[j] = wsum(p);
        }
        if (lane == 0) {
            #pragma unroll
            for (int j = 0; j < 7; j++)
                outp[(size_t)(m0 + row) * 7 + j] = r[j] + b3p[j];
        }
    }
}

// ---------------------------------------------------------------------------
extern "C" void kernel_launch(void* const* d_in, const int* in_sizes, int n_in,
                              void* d_out, int out_size)
{
    const float* f_swin    = (const float*)d_in[0];
    const float* f_maxvit  = (const float*)d_in[1];
    const float* f_focal   = (const float*)d_in[2];
    const float* in_proj_w = (const float*)d_in[3];
    const float* in_proj_b = (const float*)d_in[4];
    const float* out_w  = (const float*)d_in[5];
    const float* out_b  = (const float*)d_in[6];
    const float* ln1_g  = (const float*)d_in[7];
    const float* ln1_b  = (const float*)d_in[8];
    const float* gate_w = (const float*)d_in[9];
    const float* gate_b = (const float*)d_in[10];
    const float* ln2_g  = (const float*)d_in[11];
    const float* ln2_b  = (const float*)d_in[12];
    const float* w1 = (const float*)d_in[13];
    const float* b1 = (const float*)d_in[14];
    const float* w2 = (const float*)d_in[15];
    const float* b2 = (const float*)d_in[16];
    const float* w3 = (const float*)d_in[17];
    const float* b3 = (const float*)d_in[18];

    int B = in_sizes[0] / 256;
    if (B > BMAX) B = BMAX;
    int rows3 = 3 * B;

    float* outp = (float*)d_out;
    float* out_logits = outp;
    float* out_fused = (out_size >= B * 263) ? (outp + (size_t)B * 7) : nullptr;

    const int SMEM_QA = 81920 + 96 * QKV_STRIDE + 1024;   // 231936 <= 232448
    const int SMEM_DH = 16384 + 32768 + 65536 + 128;      // 114816 (occ 2)
    cudaFuncSetAttribute(qkv_attn_out, cudaFuncAttributeMaxDynamicSharedMemorySize, SMEM_QA);
    cudaFuncSetAttribute(deephead, cudaFuncAttributeMaxDynamicSharedMemorySize, SMEM_DH);

    dim3 blk(256);

    conv_w_all<<<352, blk>>>(in_proj_w, out_w, w1, w2);
    // fused qkv + attention + out-proj (M_TILE=96, occ 1, single-sync pipeline)
    qkv_attn_out<<<rows3 / 96, blk, SMEM_QA>>>(in_proj_b, out_b,
                                               f_swin, f_maxvit, f_focal);
    // residual + LN1 + gate + fused + LN2
    fuse_k<<<2048, blk>>>(f_swin, f_maxvit, f_focal,
                          ln1_g, ln1_b, gate_w, gate_b, ln2_g, ln2_b,
                          out_fused, B);
    // deep head fused (occ 2, single-sync pipeline)
    deephead<<<B / 64, blk, SMEM_DH>>>(b1, b2, w3, b3, out_logits);
}